// round 10
// baseline (speedup 1.0000x reference)
#include <cuda_runtime.h>
#include <cuda_bf16.h>
#include <cuda_fp16.h>
#include <cstdint>

#define TT   3072
#define HID  4096
#define NH   32
#define HD   128
#define NBAT 4
#define MAXB 24

// ============================================================================
// helpers (baseline PTX only — no sm_103a-gated features)
// ============================================================================
__device__ __forceinline__ uint32_t smem_to_u32(const void* p) {
    uint32_t a;
    asm("{ .reg .u64 t; cvta.to.shared.u64 t, %1; cvt.u32.u64 %0, t; }" : "=r"(a) : "l"(p));
    return a;
}
__device__ __forceinline__ void cp16(uint32_t dst, const void* src) {
    asm volatile("cp.async.cg.shared.global [%0], [%1], 16;" :: "r"(dst), "l"(src));
}
#define CP_COMMIT() asm volatile("cp.async.commit_group;" ::: "memory")
#define CP_WAIT1()  asm volatile("cp.async.wait_group 1;" ::: "memory")

__device__ __forceinline__ void ldsm4(uint32_t* r, uint32_t addr) {
    asm volatile("ldmatrix.sync.aligned.m8n8.x4.shared.b16 {%0,%1,%2,%3}, [%4];"
        : "=r"(r[0]), "=r"(r[1]), "=r"(r[2]), "=r"(r[3]) : "r"(addr));
}
__device__ __forceinline__ void mma_bf16(float* c, const uint32_t* a, const uint32_t* b) {
    asm volatile("mma.sync.aligned.m16n8k16.row.col.f32.bf16.bf16.f32 "
        "{%0,%1,%2,%3}, {%4,%5,%6,%7}, {%8,%9}, {%0,%1,%2,%3};"
        : "+f"(c[0]), "+f"(c[1]), "+f"(c[2]), "+f"(c[3])
        : "r"(a[0]), "r"(a[1]), "r"(a[2]), "r"(a[3]), "r"(b[0]), "r"(b[1]));
}
__device__ __forceinline__ void mma_fp16(float* c, const uint32_t* a, const uint32_t* b) {
    asm volatile("mma.sync.aligned.m16n8k16.row.col.f32.f16.f16.f32 "
        "{%0,%1,%2,%3}, {%4,%5,%6,%7}, {%8,%9}, {%0,%1,%2,%3};"
        : "+f"(c[0]), "+f"(c[1]), "+f"(c[2]), "+f"(c[3])
        : "r"(a[0]), "r"(a[1]), "r"(a[2]), "r"(a[3]), "r"(b[0]), "r"(b[1]));
}

// ---- workspace (static device arrays; no allocation) ----
__device__ float g_q[(size_t)TT * HID];
__device__ float g_k[(size_t)TT * HID];
__device__ float g_v[(size_t)TT * HID];
__device__ float g_o[(size_t)TT * HID];
__device__ float g_freq[64];
__device__ __nv_bfloat16 g_xhi[(size_t)TT * HID];
__device__ __nv_bfloat16 g_xlo[(size_t)TT * HID];
__device__ __half        g_xh [(size_t)TT * HID];
__device__ __nv_bfloat16 g_w1hi[(size_t)HID * HID];
__device__ __nv_bfloat16 g_w1lo[(size_t)HID * HID];
__device__ __nv_bfloat16 g_w2hi[(size_t)HID * HID];
__device__ __nv_bfloat16 g_w2lo[(size_t)HID * HID];
__device__ __half        g_w3h [(size_t)HID * HID];
__device__ __half        g_w4h [(size_t)HID * HID];

__global__ void init_freq_kernel() {
    int i = threadIdx.x;
    if (i < 64) g_freq[i] = (float)exp(-(double)i * (log(10000.0) / 64.0));
}

// ============================================================================
// splits
// ============================================================================
__device__ __forceinline__ void split_bf16(const float* __restrict__ x,
                                           __nv_bfloat16* __restrict__ hi,
                                           __nv_bfloat16* __restrict__ lo, int i)
{
    float4 v = ((const float4*)x)[i];
    float vv[4] = {v.x, v.y, v.z, v.w};
    __nv_bfloat16 h[4], l[4];
#pragma unroll
    for (int j = 0; j < 4; j++) {
        h[j] = __float2bfloat16(vv[j]);
        l[j] = __float2bfloat16(vv[j] - __bfloat162float(h[j]));
    }
    ((__nv_bfloat162*)hi)[2 * i + 0] = __nv_bfloat162(h[0], h[1]);
    ((__nv_bfloat162*)hi)[2 * i + 1] = __nv_bfloat162(h[2], h[3]);
    ((__nv_bfloat162*)lo)[2 * i + 0] = __nv_bfloat162(l[0], l[1]);
    ((__nv_bfloat162*)lo)[2 * i + 1] = __nv_bfloat162(l[2], l[3]);
}
__device__ __forceinline__ void conv_fp16(const float* __restrict__ x,
                                          __half* __restrict__ out, int i)
{
    float4 v = ((const float4*)x)[i];
    ((__half2*)out)[2 * i + 0] = __half2(__float2half(v.x), __float2half(v.y));
    ((__half2*)out)[2 * i + 1] = __half2(__float2half(v.z), __float2half(v.w));
}

// x -> bf16 hi/lo (for Q,K GEMMs) + fp16 single (for V GEMM), one pass
__global__ __launch_bounds__(256) void xsplit3_kernel(const float* __restrict__ x, int n4)
{
    int i = blockIdx.x * blockDim.x + threadIdx.x;
    if (i >= n4) return;
    float4 v = ((const float4*)x)[i];
    float vv[4] = {v.x, v.y, v.z, v.w};
    __nv_bfloat16 h[4], l[4];
    __half f[4];
#pragma unroll
    for (int j = 0; j < 4; j++) {
        h[j] = __float2bfloat16(vv[j]);
        l[j] = __float2bfloat16(vv[j] - __bfloat162float(h[j]));
        f[j] = __float2half(vv[j]);
    }
    ((__nv_bfloat162*)g_xhi)[2 * i + 0] = __nv_bfloat162(h[0], h[1]);
    ((__nv_bfloat162*)g_xhi)[2 * i + 1] = __nv_bfloat162(h[2], h[3]);
    ((__nv_bfloat162*)g_xlo)[2 * i + 0] = __nv_bfloat162(l[0], l[1]);
    ((__nv_bfloat162*)g_xlo)[2 * i + 1] = __nv_bfloat162(l[2], l[3]);
    ((__half2*)g_xh)[2 * i + 0] = __half2(f[0], f[1]);
    ((__half2*)g_xh)[2 * i + 1] = __half2(f[2], f[3]);
}

// attention output -> fp16 single (for O GEMM)
__global__ __launch_bounds__(256) void osplit_kernel(int n4)
{
    int i = blockIdx.x * blockDim.x + threadIdx.x;
    if (i >= n4) return;
    conv_fp16(g_o, g_xh, i);
}

// all 4 weight matrices in one launch (blockIdx.z selects); Wq/Wk bf16 pair, Wv/Wo fp16
__global__ __launch_bounds__(256) void wsplit_kernel(
    const float* __restrict__ Wq, const float* __restrict__ Wk,
    const float* __restrict__ Wv, const float* __restrict__ Wo)
{
    int i = blockIdx.x * blockDim.x + threadIdx.x;
    const int n4 = HID * HID / 4;
    if (i >= n4) return;
    int z = blockIdx.z;
    if (z == 0)      split_bf16(Wq, g_w1hi, g_w1lo, i);
    else if (z == 1) split_bf16(Wk, g_w2hi, g_w2lo, i);
    else if (z == 2) conv_fp16(Wv, g_w3h, i);
    else             conv_fp16(Wo, g_w4h, i);
}

// ============================================================================
// GEMM common geometry: CTA 128x128, BK=64, 8 warps (2x4), warp tile 64x32,
// cp.async 3-stage, single __syncthreads per iteration.
// gemm3 adds register double-buffered fragments (LDSM for ks+1 overlaps MMA of ks).
// ============================================================================
#define TILE_B  16384

// ---- bf16 3-term kernel (Q,K): stage = 4 tiles (Ahi,Alo,Bhi,Blo) ----
#define STAGE3_B (4 * TILE_B)
#define GEMM3_SMEM (3 * STAGE3_B)   // 196608

__global__ __launch_bounds__(256)
void gemm3(const __nv_bfloat16* __restrict__ Ahi, const __nv_bfloat16* __restrict__ Alo,
           const __nv_bfloat16* __restrict__ Bhi, const __nv_bfloat16* __restrict__ Blo,
           const float* __restrict__ bias, float* __restrict__ C)
{
    extern __shared__ char smem[];
    const uint32_t sb = smem_to_u32(smem);
    const int tid = threadIdx.x;
    const int wid = tid >> 5;
    const int lane = tid & 31;
    const int m0 = blockIdx.y << 7;
    const int n0 = blockIdx.x << 7;
    const int wm = wid >> 2;
    const int wn = wid & 3;

    const int lrow = tid >> 1;
    const int lcb  = (tid & 1) * 4;
    const uint32_t lrsw = (uint32_t)(lrow & 7) << 4;
    const __nv_bfloat16* gsrc[4];
    gsrc[0] = Ahi + (size_t)(m0 + lrow) * HID + lcb * 8;
    gsrc[1] = Alo + (size_t)(m0 + lrow) * HID + lcb * 8;
    gsrc[2] = Bhi + (size_t)(n0 + lrow) * HID + lcb * 8;
    gsrc[3] = Blo + (size_t)(n0 + lrow) * HID + lcb * 8;
    uint32_t ldst[4][4];
#pragma unroll
    for (int t = 0; t < 4; t++)
#pragma unroll
        for (int j = 0; j < 4; j++)
            ldst[t][j] = t * TILE_B + lrow * 128 + ((uint32_t)((lcb + j) * 16) ^ lrsw);

    uint32_t a_off[4], a_sw[4];
#pragma unroll
    for (int mt = 0; mt < 4; mt++) {
        int m = wm * 64 + mt * 16 + (lane & 15);
        a_off[mt] = (uint32_t)m * 128;
        a_sw[mt]  = (uint32_t)(m & 7) << 4;
    }
    const uint32_t ka = (uint32_t)((lane >> 4) << 4);
    uint32_t b_off[2], b_sw[2];
#pragma unroll
    for (int p = 0; p < 2; p++) {
        int n = wn * 32 + p * 16 + (lane & 7) + ((lane & 16) >> 1);
        b_off[p] = (uint32_t)n * 128;
        b_sw[p]  = (uint32_t)(n & 7) << 4;
    }
    const uint32_t kb = (uint32_t)((lane & 8) << 1);

    float acc[4][4][4];
#pragma unroll
    for (int i = 0; i < 4; i++)
#pragma unroll
        for (int j = 0; j < 4; j++)
#pragma unroll
            for (int k = 0; k < 4; k++) acc[i][j][k] = 0.f;

#pragma unroll
    for (int s = 0; s < 2; s++) {
        uint32_t base = sb + s * STAGE3_B;
#pragma unroll
        for (int t = 0; t < 4; t++) {
            const __nv_bfloat16* src = gsrc[t] + s * 64;
#pragma unroll
            for (int j = 0; j < 4; j++)
                cp16(base + ldst[t][j], src + j * 8);
        }
        CP_COMMIT();
    }

    // double-buffered fragments
    uint32_t ahi[2][4][4], alo[2][4][4], bhi[2][2][4], blo[2][2][4];

    for (int c = 0; c < 64; c++) {
        CP_WAIT1();
        __syncthreads();
        const int ldc = c + 2;
        if (ldc < 64) {
            uint32_t base = sb + (ldc % 3) * STAGE3_B;
#pragma unroll
            for (int t = 0; t < 4; t++) {
                const __nv_bfloat16* src = gsrc[t] + ldc * 64;
#pragma unroll
                for (int j = 0; j < 4; j++)
                    cp16(base + ldst[t][j], src + j * 8);
            }
        }
        CP_COMMIT();

        const uint32_t stb = sb + (c % 3) * STAGE3_B;

        // preload ks=0 fragments into buffer 0
#pragma unroll
        for (int mt = 0; mt < 4; mt++) {
            uint32_t ko = ka ^ a_sw[mt];
            uint32_t ad = stb + a_off[mt] + ko;
            ldsm4(ahi[0][mt], ad);
            ldsm4(alo[0][mt], ad + TILE_B);
        }
#pragma unroll
        for (int p = 0; p < 2; p++) {
            uint32_t ko = kb ^ b_sw[p];
            uint32_t bd = stb + 2 * TILE_B + b_off[p] + ko;
            ldsm4(bhi[0][p], bd);
            ldsm4(blo[0][p], bd + TILE_B);
        }

#pragma unroll
        for (int ks = 0; ks < 4; ks++) {
            const int cur = ks & 1;
            const int nxt = cur ^ 1;
            if (ks < 3) {
                // issue LDSMs for ks+1 before the MMA block; they complete
                // while the tensor pipe drains the current 48 MMAs
#pragma unroll
                for (int mt = 0; mt < 4; mt++) {
                    uint32_t ko = ((uint32_t)((ks + 1) * 32) + ka) ^ a_sw[mt];
                    uint32_t ad = stb + a_off[mt] + ko;
                    ldsm4(ahi[nxt][mt], ad);
                    ldsm4(alo[nxt][mt], ad + TILE_B);
                }
#pragma unroll
                for (int p = 0; p < 2; p++) {
                    uint32_t ko = ((uint32_t)((ks + 1) * 32) + kb) ^ b_sw[p];
                    uint32_t bd = stb + 2 * TILE_B + b_off[p] + ko;
                    ldsm4(bhi[nxt][p], bd);
                    ldsm4(blo[nxt][p], bd + TILE_B);
                }
            }
#pragma unroll
            for (int mt = 0; mt < 4; mt++)
#pragma unroll
                for (int nt = 0; nt < 4; nt++) {
                    const uint32_t* bh = &bhi[cur][nt >> 1][2 * (nt & 1)];
                    const uint32_t* bl = &blo[cur][nt >> 1][2 * (nt & 1)];
                    mma_bf16(acc[mt][nt], ahi[cur][mt], bh);
                    mma_bf16(acc[mt][nt], ahi[cur][mt], bl);
                    mma_bf16(acc[mt][nt], alo[cur][mt], bh);
                }
        }
    }

#pragma unroll
    for (int mt = 0; mt < 4; mt++) {
#pragma unroll
        for (int nt = 0; nt < 4; nt++) {
            int row = m0 + wm * 64 + mt * 16 + (lane >> 2);
            int col = n0 + wn * 32 + nt * 8 + 2 * (lane & 3);
            float2 bv = *(const float2*)&bias[col];
            float2 v0, v1;
            v0.x = acc[mt][nt][0] + bv.x; v0.y = acc[mt][nt][1] + bv.y;
            v1.x = acc[mt][nt][2] + bv.x; v1.y = acc[mt][nt][3] + bv.y;
            *(float2*)&C[(size_t)row * HID + col]       = v0;
            *(float2*)&C[(size_t)(row + 8) * HID + col] = v1;
        }
    }
}

// ---- fp16 1-term kernel (V,O): plain A x B^T; stage = 2 tiles = 32KB ----
// 3 stages = 96KB; regs <=128 -> 2 CTAs/SM (launch_bounds minBlocks=2)
#define STAGE1_B (2 * TILE_B)
#define GEMM1_SMEM (3 * STAGE1_B)   // 98304

__global__ __launch_bounds__(256, 2)
void gemm1h(const __half* __restrict__ A, const __half* __restrict__ B,
            const float* __restrict__ bias, float* __restrict__ C)
{
    extern __shared__ char smem[];
    const uint32_t sb = smem_to_u32(smem);
    const int tid = threadIdx.x;
    const int wid = tid >> 5;
    const int lane = tid & 31;
    const int m0 = blockIdx.y << 7;
    const int n0 = blockIdx.x << 7;
    const int wm = wid >> 2;
    const int wn = wid & 3;

    const int lrow = tid >> 1;
    const int lcb  = (tid & 1) * 4;
    const uint32_t lrsw = (uint32_t)(lrow & 7) << 4;
    const __half* gsrc[2];
    gsrc[0] = A + (size_t)(m0 + lrow) * HID + lcb * 8;
    gsrc[1] = B + (size_t)(n0 + lrow) * HID + lcb * 8;
    uint32_t ldst[2][4];
#pragma unroll
    for (int t = 0; t < 2; t++)
#pragma unroll
        for (int j = 0; j < 4; j++)
            ldst[t][j] = t * TILE_B + lrow * 128 + ((uint32_t)((lcb + j) * 16) ^ lrsw);

    uint32_t a_off[4], a_sw[4];
#pragma unroll
    for (int mt = 0; mt < 4; mt++) {
        int m = wm * 64 + mt * 16 + (lane & 15);
        a_off[mt] = (uint32_t)m * 128;
        a_sw[mt]  = (uint32_t)(m & 7) << 4;
    }
    const uint32_t ka = (uint32_t)((lane >> 4) << 4);
    uint32_t b_off[2], b_sw[2];
#pragma unroll
    for (int p = 0; p < 2; p++) {
        int n = wn * 32 + p * 16 + (lane & 7) + ((lane & 16) >> 1);
        b_off[p] = (uint32_t)n * 128;
        b_sw[p]  = (uint32_t)(n & 7) << 4;
    }
    const uint32_t kb = (uint32_t)((lane & 8) << 1);

    float acc[4][4][4];
#pragma unroll
    for (int i = 0; i < 4; i++)
#pragma unroll
        for (int j = 0; j < 4; j++)
#pragma unroll
            for (int k = 0; k < 4; k++) acc[i][j][k] = 0.f;

#pragma unroll
    for (int s = 0; s < 2; s++) {
        uint32_t base = sb + s * STAGE1_B;
#pragma unroll
        for (int t = 0; t < 2; t++) {
            const __half* src = gsrc[t] + s * 64;
#pragma unroll
            for (int j = 0; j < 4; j++)
                cp16(base + ldst[t][j], src + j * 8);
        }
        CP_COMMIT();
    }

    for (int c = 0; c < 64; c++) {
        CP_WAIT1();
        __syncthreads();
        const int ldc = c + 2;
        if (ldc < 64) {
            uint32_t base = sb + (ldc % 3) * STAGE1_B;
#pragma unroll
            for (int t = 0; t < 2; t++) {
                const __half* src = gsrc[t] + ldc * 64;
#pragma unroll
                for (int j = 0; j < 4; j++)
                    cp16(base + ldst[t][j], src + j * 8);
            }
        }
        CP_COMMIT();

        const uint32_t stb = sb + (c % 3) * STAGE1_B;
#pragma unroll
        for (int ks = 0; ks < 4; ks++) {
            uint32_t af[4][4];
#pragma unroll
            for (int mt = 0; mt < 4; mt++) {
                uint32_t ko = ((uint32_t)(ks * 32) + ka) ^ a_sw[mt];
                ldsm4(af[mt], stb + a_off[mt] + ko);
            }
            uint32_t bf[2][4];
#pragma unroll
            for (int p = 0; p < 2; p++) {
                uint32_t ko = ((uint32_t)(ks * 32) + kb) ^ b_sw[p];
                ldsm4(bf[p], stb + TILE_B + b_off[p] + ko);
            }
#pragma unroll
            for (int mt = 0; mt < 4; mt++)
#pragma unroll
                for (int nt = 0; nt < 4; nt++)
                    mma_fp16(acc[mt][nt], af[mt], &bf[nt >> 1][2 * (nt & 1)]);
        }
    }

#pragma unroll
    for (int mt = 0; mt < 4; mt++) {
#pragma unroll
        for (int nt = 0; nt < 4; nt++) {
            int row = m0 + wm * 64 + mt * 16 + (lane >> 2);
            int col = n0 + wn * 32 + nt * 8 + 2 * (lane & 3);
            float2 bv = *(const float2*)&bias[col];
            float2 v0, v1;
            v0.x = acc[mt][nt][0] + bv.x; v0.y = acc[mt][nt][1] + bv.y;
            v1.x = acc[mt][nt][2] + bv.x; v1.y = acc[mt][nt][3] + bv.y;
            *(float2*)&C[(size_t)row * HID + col]       = v0;
            *(float2*)&C[(size_t)(row + 8) * HID + col] = v1;
        }
    }
}

// ============================================================================
// RoPE on packed q,k in place (angle in f32 like reference, trig in double)
// ============================================================================
__global__ void rope_kernel(const int* __restrict__ pos) {
    int idx = blockIdx.x * blockDim.x + threadIdx.x;
    if (idx >= TT * NH * 64) return;
    int i = idx & 63;
    int h = (idx >> 6) & 31;
    int t = idx >> 11;
    float p = (float)pos[t];
    float ang = p * g_freq[i];
    double ad = (double)ang;
    float c = (float)cos(ad);
    float s = (float)sin(ad);
    size_t base = ((size_t)t * NH + h) * HD;
    float x1 = g_q[base + i], x2 = g_q[base + 64 + i];
    g_q[base + i]      = x1 * c - x2 * s;
    g_q[base + 64 + i] = x2 * c + x1 * s;
    float y1 = g_k[base + i], y2 = g_k[base + 64 + i];
    g_k[base + i]      = y1 * c - y2 * s;
    g_k[base + 64 + i] = y2 * c + y1 * s;
}

// ============================================================================
// Flash attention (fp32), validated in round 1
// ============================================================================
#define ATTN_SMEM_FLOATS (8192 + 8448 + 4224 + 192)
#define ATTN_SMEM_BYTES  (ATTN_SMEM_FLOATS * 4)

__global__ __launch_bounds__(128) void attn_kernel(
    const float* __restrict__ past_k, const float* __restrict__ past_v,
    const int* __restrict__ q_start, const int* __restrict__ q_lens,
    const int* __restrict__ kv_lens, const int* __restrict__ boff)
{
    extern __shared__ float sm[];
    float* Qs   = sm;
    float* KVs  = sm + 8192;
    float* Ps   = KVs + 8448;
    float* mrow = Ps + 4224;
    float* lrow = mrow + 64;
    float* arow = lrow + 64;

    const int b = blockIdx.z, h = blockIdx.y, qt = blockIdx.x;
    const int qlen = q_lens[b];
    if (qt * 64 >= qlen) return;
    const int qs0 = q_start[b];
    const int kvlen = kv_lens[b];
    const int hist = kvlen - qlen;
    const int tid = threadIdx.x;
    const float scale = 0.08838834764831845f;
    const float NEGINF = __int_as_float(0xff800000);

    const int c4 = (tid & 31) << 2;
    const int r0 = tid >> 5;

#pragma unroll
    for (int rr = 0; rr < 16; rr++) {
        int r = r0 + rr * 4;
        int qglob = qt * 64 + r;
        float4 v = make_float4(0.f, 0.f, 0.f, 0.f);
        if (qglob < qlen)
            v = *(const float4*)&g_q[((size_t)(qs0 + qglob) * NH + h) * HD + c4];
        *(float4*)&Qs[r * 128 + c4] = v;
    }
    if (tid < 64) { mrow[tid] = NEGINF; lrow[tid] = 0.f; }
    __syncthreads();

    const int tq = tid >> 3;
    const int tk = tid & 7;

    float o[4][16];
#pragma unroll
    for (int i = 0; i < 4; i++)
#pragma unroll
        for (int j = 0; j < 16; j++) o[i][j] = 0.f;

    const int qhi  = min(qt * 64 + 63, qlen - 1);
    const int nblk = min((kvlen + 63) >> 6, ((hist + qhi) >> 6) + 1);

    for (int kb = 0; kb < nblk; kb++) {
#pragma unroll
        for (int rr = 0; rr < 16; rr++) {
            int r = r0 + rr * 4;
            int p = kb * 64 + r;
            int pc = min(p, kvlen - 1);
            const float* src;
            if (pc < hist) {
                int blk = boff[b * MAXB + (pc >> 6)];
                src = past_k + ((size_t)(blk * 64 + (pc & 63)) * NH + h) * HD;
            } else {
                src = g_k + ((size_t)(qs0 + pc - hist) * NH + h) * HD;
            }
            *(float4*)&KVs[r * 132 + c4] = *(const float4*)&src[c4];
        }
        __syncthreads();

        float s[4][8];
#pragma unroll
        for (int i = 0; i < 4; i++)
#pragma unroll
            for (int m = 0; m < 8; m++) s[i][m] = 0.f;
#pragma unroll 4
        for (int d = 0; d < 128; d += 4) {
            float4 qv[4];
#pragma unroll
            for (int i = 0; i < 4; i++)
                qv[i] = *(const float4*)&Qs[(tq * 4 + i) * 128 + d];
#pragma unroll
            for (int m = 0; m < 8; m++) {
                float4 kv = *(const float4*)&KVs[(tk + 8 * m) * 132 + d];
#pragma unroll
                for (int i = 0; i < 4; i++)
                    s[i][m] += qv[i].x * kv.x + qv[i].y * kv.y + qv[i].z * kv.z + qv[i].w * kv.w;
            }
        }
#pragma unroll
        for (int i = 0; i < 4; i++) {
            int qglob = qt * 64 + tq * 4 + i;
#pragma unroll
            for (int m = 0; m < 8; m++) {
                int kg = kb * 64 + tk + 8 * m;
                float val = (kg <= hist + qglob) ? s[i][m] * scale : NEGINF;
                Ps[(tq * 4 + i) * 66 + tk + 8 * m] = val;
            }
        }
        __syncthreads();

#pragma unroll
        for (int rr = 0; rr < 16; rr++) {
            int r = r0 + rr * 4;
            int p = kb * 64 + r;
            int pc = min(p, kvlen - 1);
            const float* src;
            if (pc < hist) {
                int blk = boff[b * MAXB + (pc >> 6)];
                src = past_v + ((size_t)(blk * 64 + (pc & 63)) * NH + h) * HD;
            } else {
                src = g_v + ((size_t)(qs0 + pc - hist) * NH + h) * HD;
            }
            *(float4*)&KVs[r * 132 + c4] = *(const float4*)&src[c4];
        }

        if (tid < 64) {
            int r = tid;
            float mo = mrow[r];
            float mx = mo;
#pragma unroll 8
            for (int j = 0; j < 64; j++) mx = fmaxf(mx, Ps[r * 66 + j]);
            float alpha = expf(mo - mx);
            float sum = 0.f;
#pragma unroll 8
            for (int j = 0; j < 64; j++) {
                float pj = expf(Ps[r * 66 + j] - mx);
                Ps[r * 66 + j] = pj;
                sum += pj;
            }
            mrow[r] = mx;
            lrow[r] = lrow[r] * alpha + sum;
            arow[r] = alpha;
        }
        __syncthreads();

#pragma unroll
        for (int i = 0; i < 4; i++) {
            float a = arow[tq * 4 + i];
#pragma unroll
            for (int j = 0; j < 16; j++) o[i][j] *= a;
        }
#pragma unroll 2
        for (int k = 0; k < 64; k++) {
            float pr[4];
#pragma unroll
            for (int i = 0; i < 4; i++) pr[i] = Ps[(tq * 4 + i) * 66 + k];
#pragma unroll
            for (int m = 0; m < 4; m++) {
                float4 vv = *(const float4*)&KVs[k * 132 + tk * 4 + 32 * m];
#pragma unroll
                for (int i = 0; i < 4; i++) {
                    o[i][m * 4 + 0] += pr[i] * vv.x;
                    o[i][m * 4 + 1] += pr[i] * vv.y;
                    o[i][m * 4 + 2] += pr[i] * vv.z;
                    o[i][m * 4 + 3] += pr[i] * vv.w;
                }
            }
        }
        __syncthreads();
    }

#pragma unroll
    for (int i = 0; i < 4; i++) {
        int qglob = qt * 64 + tq * 4 + i;
        if (qglob >= qlen) continue;
        float inv = 1.f / lrow[tq * 4 + i];
        size_t base = ((size_t)(qs0 + qglob) * NH + h) * HD;
#pragma unroll
        for (int m = 0; m < 4; m++) {
            float4 w;
            w.x = o[i][m * 4 + 0] * inv;
            w.y = o[i][m * 4 + 1] * inv;
            w.z = o[i][m * 4 + 2] * inv;
            w.w = o[i][m * 4 + 3] * inv;
            *(float4*)&g_o[base + tk * 4 + 32 * m] = w;
        }
    }
}

// ============================================================================
extern "C" void kernel_launch(void* const* d_in, const int* in_sizes, int n_in,
                              void* d_out, int out_size) {
    const float* x      = (const float*)d_in[0];
    const int*   pos    = (const int*)d_in[1];
    const int*   qstart = (const int*)d_in[2];
    const int*   qlens  = (const int*)d_in[3];
    const int*   kvlens = (const int*)d_in[4];
    const int*   boff   = (const int*)d_in[5];
    const float* pk     = (const float*)d_in[6];
    const float* pv     = (const float*)d_in[7];
    const float* Wq = (const float*)d_in[8];
    const float* bq = (const float*)d_in[9];
    const float* Wk = (const float*)d_in[10];
    const float* bk = (const float*)d_in[11];
    const float* Wv = (const float*)d_in[12];
    const float* bv = (const float*)d_in[13];
    const float* Wo = (const float*)d_in[14];
    const float* bo = (const float*)d_in[15];
    float* out = (float*)d_out;

    float *qp, *kp, *vp;
    cudaGetSymbolAddress((void**)&qp, g_q);
    cudaGetSymbolAddress((void**)&kp, g_k);
    cudaGetSymbolAddress((void**)&vp, g_v);
    __nv_bfloat16 *xhi, *xlo, *w1hi, *w1lo, *w2hi, *w2lo;
    __half *xh, *w3h, *w4h;
    cudaGetSymbolAddress((void**)&xhi, g_xhi);
    cudaGetSymbolAddress((void**)&xlo, g_xlo);
    cudaGetSymbolAddress((void**)&xh,  g_xh);
    cudaGetSymbolAddress((void**)&w1hi, g_w1hi);
    cudaGetSymbolAddress((void**)&w1lo, g_w1lo);
    cudaGetSymbolAddress((void**)&w2hi, g_w2hi);
    cudaGetSymbolAddress((void**)&w2lo, g_w2lo);
    cudaGetSymbolAddress((void**)&w3h, g_w3h);
    cudaGetSymbolAddress((void**)&w4h, g_w4h);

    cudaFuncSetAttribute(gemm3,  cudaFuncAttributeMaxDynamicSharedMemorySize, GEMM3_SMEM);
    cudaFuncSetAttribute(gemm1h, cudaFuncAttributeMaxDynamicSharedMemorySize, GEMM1_SMEM);
    cudaFuncSetAttribute(attn_kernel, cudaFuncAttributeMaxDynamicSharedMemorySize, ATTN_SMEM_BYTES);

    const int n4x = TT * HID / 4;
    const int n4w = HID * HID / 4;
    dim3 gg(HID / 128, TT / 128);   // (32, 24)

    // 0: weight splits, 1: activation split (bf16 pair + fp16)
    wsplit_kernel<<<dim3((n4w + 255) / 256, 1, 4), 256>>>(Wq, Wk, Wv, Wo);
    xsplit3_kernel<<<(n4x + 255) / 256, 256>>>(x, n4x);
    // 2,3: Q/K GEMMs (bf16 3-term, frag double-buffered), 4: V GEMM (fp16 1-term)
    gemm3<<<gg, 256, GEMM3_SMEM>>>(xhi, xlo, w1hi, w1lo, bq, qp);
    gemm3<<<gg, 256, GEMM3_SMEM>>>(xhi, xlo, w2hi, w2lo, bk, kp);
    gemm1h<<<gg, 256, GEMM1_SMEM>>>(xh, w3h, bv, vp);
    // 5: freq, 6: rope, 7: attention
    init_freq_kernel<<<1, 64>>>();
    rope_kernel<<<(TT * NH * 64 + 255) / 256, 256>>>(pos);
    attn_kernel<<<dim3(16, NH, NBAT), 128, ATTN_SMEM_BYTES>>>(pk, pv, qstart, qlens,
                                                              kvlens, boff);
    // 8: attention output -> fp16, 9: O GEMM (fp16 1-term)
    osplit_kernel<<<(n4x + 255) / 256, 256>>>(n4x);
    gemm1h<<<gg, 256, GEMM1_SMEM>>>(xh, w4h, bo, out);
}

// round 12
// speedup vs baseline: 1.0406x; 1.0406x over previous
#include <cuda_runtime.h>
#include <cuda_bf16.h>
#include <cuda_fp16.h>
#include <cstdint>

#define TT   3072
#define HID  4096
#define NH   32
#define HD   128
#define NBAT 4
#define MAXB 24

// ============================================================================
// helpers (baseline PTX only — no sm_103a-gated features)
// ============================================================================
__device__ __forceinline__ uint32_t smem_to_u32(const void* p) {
    uint32_t a;
    asm("{ .reg .u64 t; cvta.to.shared.u64 t, %1; cvt.u32.u64 %0, t; }" : "=r"(a) : "l"(p));
    return a;
}
__device__ __forceinline__ void cp16(uint32_t dst, const void* src) {
    asm volatile("cp.async.cg.shared.global [%0], [%1], 16;" :: "r"(dst), "l"(src));
}
#define CP_COMMIT() asm volatile("cp.async.commit_group;" ::: "memory")
#define CP_WAIT1()  asm volatile("cp.async.wait_group 1;" ::: "memory")

__device__ __forceinline__ void ldsm4(uint32_t* r, uint32_t addr) {
    asm volatile("ldmatrix.sync.aligned.m8n8.x4.shared.b16 {%0,%1,%2,%3}, [%4];"
        : "=r"(r[0]), "=r"(r[1]), "=r"(r[2]), "=r"(r[3]) : "r"(addr));
}
__device__ __forceinline__ void mma_bf16(float* c, const uint32_t* a, const uint32_t* b) {
    asm volatile("mma.sync.aligned.m16n8k16.row.col.f32.bf16.bf16.f32 "
        "{%0,%1,%2,%3}, {%4,%5,%6,%7}, {%8,%9}, {%0,%1,%2,%3};"
        : "+f"(c[0]), "+f"(c[1]), "+f"(c[2]), "+f"(c[3])
        : "r"(a[0]), "r"(a[1]), "r"(a[2]), "r"(a[3]), "r"(b[0]), "r"(b[1]));
}
__device__ __forceinline__ void mma_fp16(float* c, const uint32_t* a, const uint32_t* b) {
    asm volatile("mma.sync.aligned.m16n8k16.row.col.f32.f16.f16.f32 "
        "{%0,%1,%2,%3}, {%4,%5,%6,%7}, {%8,%9}, {%0,%1,%2,%3};"
        : "+f"(c[0]), "+f"(c[1]), "+f"(c[2]), "+f"(c[3])
        : "r"(a[0]), "r"(a[1]), "r"(a[2]), "r"(a[3]), "r"(b[0]), "r"(b[1]));
}

// ---- workspace (static device arrays; no allocation) ----
__device__ float g_q[(size_t)TT * HID];
__device__ float g_k[(size_t)TT * HID];
__device__ float g_v[(size_t)TT * HID];
__device__ float g_freq[64];
__device__ __nv_bfloat16 g_xhi[(size_t)TT * HID];
__device__ __nv_bfloat16 g_xlo[(size_t)TT * HID];
__device__ __half        g_xh [(size_t)TT * HID];
__device__ __nv_bfloat16 g_w1hi[(size_t)HID * HID];
__device__ __nv_bfloat16 g_w1lo[(size_t)HID * HID];
__device__ __nv_bfloat16 g_w2hi[(size_t)HID * HID];
__device__ __nv_bfloat16 g_w2lo[(size_t)HID * HID];
__device__ __half        g_w3h [(size_t)HID * HID];
__device__ __half        g_w4h [(size_t)HID * HID];

__global__ void init_freq_kernel() {
    int i = threadIdx.x;
    if (i < 64) g_freq[i] = (float)exp(-(double)i * (log(10000.0) / 64.0));
}

// ============================================================================
// splits
// ============================================================================
__device__ __forceinline__ void split_bf16(const float* __restrict__ x,
                                           __nv_bfloat16* __restrict__ hi,
                                           __nv_bfloat16* __restrict__ lo, int i)
{
    float4 v = ((const float4*)x)[i];
    float vv[4] = {v.x, v.y, v.z, v.w};
    __nv_bfloat16 h[4], l[4];
#pragma unroll
    for (int j = 0; j < 4; j++) {
        h[j] = __float2bfloat16(vv[j]);
        l[j] = __float2bfloat16(vv[j] - __bfloat162float(h[j]));
    }
    ((__nv_bfloat162*)hi)[2 * i + 0] = __nv_bfloat162(h[0], h[1]);
    ((__nv_bfloat162*)hi)[2 * i + 1] = __nv_bfloat162(h[2], h[3]);
    ((__nv_bfloat162*)lo)[2 * i + 0] = __nv_bfloat162(l[0], l[1]);
    ((__nv_bfloat162*)lo)[2 * i + 1] = __nv_bfloat162(l[2], l[3]);
}
__device__ __forceinline__ void conv_fp16(const float* __restrict__ x,
                                          __half* __restrict__ out, int i)
{
    float4 v = ((const float4*)x)[i];
    ((__half2*)out)[2 * i + 0] = __half2(__float2half(v.x), __float2half(v.y));
    ((__half2*)out)[2 * i + 1] = __half2(__float2half(v.z), __float2half(v.w));
}

// x -> bf16 hi/lo (Q,K GEMMs) + fp16 single (V GEMM), one pass
__global__ __launch_bounds__(256) void xsplit3_kernel(const float* __restrict__ x, int n4)
{
    int i = blockIdx.x * blockDim.x + threadIdx.x;
    if (i >= n4) return;
    float4 v = ((const float4*)x)[i];
    float vv[4] = {v.x, v.y, v.z, v.w};
    __nv_bfloat16 h[4], l[4];
    __half f[4];
#pragma unroll
    for (int j = 0; j < 4; j++) {
        h[j] = __float2bfloat16(vv[j]);
        l[j] = __float2bfloat16(vv[j] - __bfloat162float(h[j]));
        f[j] = __float2half(vv[j]);
    }
    ((__nv_bfloat162*)g_xhi)[2 * i + 0] = __nv_bfloat162(h[0], h[1]);
    ((__nv_bfloat162*)g_xhi)[2 * i + 1] = __nv_bfloat162(h[2], h[3]);
    ((__nv_bfloat162*)g_xlo)[2 * i + 0] = __nv_bfloat162(l[0], l[1]);
    ((__nv_bfloat162*)g_xlo)[2 * i + 1] = __nv_bfloat162(l[2], l[3]);
    ((__half2*)g_xh)[2 * i + 0] = __half2(f[0], f[1]);
    ((__half2*)g_xh)[2 * i + 1] = __half2(f[2], f[3]);
}

// all 4 weight matrices in one launch (blockIdx.z selects); Wq/Wk bf16 pair, Wv/Wo fp16
__global__ __launch_bounds__(256) void wsplit_kernel(
    const float* __restrict__ Wq, const float* __restrict__ Wk,
    const float* __restrict__ Wv, const float* __restrict__ Wo)
{
    int i = blockIdx.x * blockDim.x + threadIdx.x;
    const int n4 = HID * HID / 4;
    if (i >= n4) return;
    int z = blockIdx.z;
    if (z == 0)      split_bf16(Wq, g_w1hi, g_w1lo, i);
    else if (z == 1) split_bf16(Wk, g_w2hi, g_w2lo, i);
    else if (z == 2) conv_fp16(Wv, g_w3h, i);
    else             conv_fp16(Wo, g_w4h, i);
}

// ============================================================================
// GEMM geometry: CTA 128x128, BK=64, 8 warps (2x4), warp tile 64x32,
// cp.async 3-stage, single __syncthreads per iteration (R7 pipeline).
// ============================================================================
#define TILE_B  16384

// ---- bf16 3-term kernel, Q and K fused via blockIdx.z ----
#define STAGE3_B (4 * TILE_B)
#define GEMM3_SMEM (3 * STAGE3_B)   // 196608

__global__ __launch_bounds__(256)
void gemm3qk(const __nv_bfloat16* __restrict__ Ahi, const __nv_bfloat16* __restrict__ Alo,
             const float* __restrict__ bq, const float* __restrict__ bk)
{
    const int zz = blockIdx.z;
    const __nv_bfloat16* __restrict__ Bhi = zz ? g_w2hi : g_w1hi;
    const __nv_bfloat16* __restrict__ Blo = zz ? g_w2lo : g_w1lo;
    const float* __restrict__ bias = zz ? bk : bq;
    float* __restrict__ C = zz ? g_k : g_q;

    extern __shared__ char smem[];
    const uint32_t sb = smem_to_u32(smem);
    const int tid = threadIdx.x;
    const int wid = tid >> 5;
    const int lane = tid & 31;
    const int m0 = blockIdx.y << 7;
    const int n0 = blockIdx.x << 7;
    const int wm = wid >> 2;
    const int wn = wid & 3;

    const int lrow = tid >> 1;
    const int lcb  = (tid & 1) * 4;
    const uint32_t lrsw = (uint32_t)(lrow & 7) << 4;
    const __nv_bfloat16* gsrc[4];
    gsrc[0] = Ahi + (size_t)(m0 + lrow) * HID + lcb * 8;
    gsrc[1] = Alo + (size_t)(m0 + lrow) * HID + lcb * 8;
    gsrc[2] = Bhi + (size_t)(n0 + lrow) * HID + lcb * 8;
    gsrc[3] = Blo + (size_t)(n0 + lrow) * HID + lcb * 8;
    uint32_t ldst[4][4];
#pragma unroll
    for (int t = 0; t < 4; t++)
#pragma unroll
        for (int j = 0; j < 4; j++)
            ldst[t][j] = t * TILE_B + lrow * 128 + ((uint32_t)((lcb + j) * 16) ^ lrsw);

    uint32_t a_off[4], a_sw[4];
#pragma unroll
    for (int mt = 0; mt < 4; mt++) {
        int m = wm * 64 + mt * 16 + (lane & 15);
        a_off[mt] = (uint32_t)m * 128;
        a_sw[mt]  = (uint32_t)(m & 7) << 4;
    }
    const uint32_t ka = (uint32_t)((lane >> 4) << 4);
    uint32_t b_off[2], b_sw[2];
#pragma unroll
    for (int p = 0; p < 2; p++) {
        int n = wn * 32 + p * 16 + (lane & 7) + ((lane & 16) >> 1);
        b_off[p] = (uint32_t)n * 128;
        b_sw[p]  = (uint32_t)(n & 7) << 4;
    }
    const uint32_t kb = (uint32_t)((lane & 8) << 1);

    float acc[4][4][4];
#pragma unroll
    for (int i = 0; i < 4; i++)
#pragma unroll
        for (int j = 0; j < 4; j++)
#pragma unroll
            for (int k = 0; k < 4; k++) acc[i][j][k] = 0.f;

#pragma unroll
    for (int s = 0; s < 2; s++) {
        uint32_t base = sb + s * STAGE3_B;
#pragma unroll
        for (int t = 0; t < 4; t++) {
            const __nv_bfloat16* src = gsrc[t] + s * 64;
#pragma unroll
            for (int j = 0; j < 4; j++)
                cp16(base + ldst[t][j], src + j * 8);
        }
        CP_COMMIT();
    }

    for (int c = 0; c < 64; c++) {
        CP_WAIT1();
        __syncthreads();
        const int ldc = c + 2;
        if (ldc < 64) {
            uint32_t base = sb + (ldc % 3) * STAGE3_B;
#pragma unroll
            for (int t = 0; t < 4; t++) {
                const __nv_bfloat16* src = gsrc[t] + ldc * 64;
#pragma unroll
                for (int j = 0; j < 4; j++)
                    cp16(base + ldst[t][j], src + j * 8);
            }
        }
        CP_COMMIT();

        const uint32_t stb = sb + (c % 3) * STAGE3_B;
#pragma unroll
        for (int ks = 0; ks < 4; ks++) {
            uint32_t ahi[4][4], alo[4][4];
#pragma unroll
            for (int mt = 0; mt < 4; mt++) {
                uint32_t ko = ((uint32_t)(ks * 32) + ka) ^ a_sw[mt];
                uint32_t ad = stb + a_off[mt] + ko;
                ldsm4(ahi[mt], ad);
                ldsm4(alo[mt], ad + TILE_B);
            }
            uint32_t bhi[2][4], blo[2][4];
#pragma unroll
            for (int p = 0; p < 2; p++) {
                uint32_t ko = ((uint32_t)(ks * 32) + kb) ^ b_sw[p];
                uint32_t bd = stb + 2 * TILE_B + b_off[p] + ko;
                ldsm4(bhi[p], bd);
                ldsm4(blo[p], bd + TILE_B);
            }
#pragma unroll
            for (int mt = 0; mt < 4; mt++)
#pragma unroll
                for (int nt = 0; nt < 4; nt++) {
                    const uint32_t* bh = &bhi[nt >> 1][2 * (nt & 1)];
                    const uint32_t* bl = &blo[nt >> 1][2 * (nt & 1)];
                    mma_bf16(acc[mt][nt], ahi[mt], bh);
                    mma_bf16(acc[mt][nt], ahi[mt], bl);
                    mma_bf16(acc[mt][nt], alo[mt], bh);
                }
        }
    }

#pragma unroll
    for (int mt = 0; mt < 4; mt++) {
#pragma unroll
        for (int nt = 0; nt < 4; nt++) {
            int row = m0 + wm * 64 + mt * 16 + (lane >> 2);
            int col = n0 + wn * 32 + nt * 8 + 2 * (lane & 3);
            float2 bv = *(const float2*)&bias[col];
            float2 v0, v1;
            v0.x = acc[mt][nt][0] + bv.x; v0.y = acc[mt][nt][1] + bv.y;
            v1.x = acc[mt][nt][2] + bv.x; v1.y = acc[mt][nt][3] + bv.y;
            *(float2*)&C[(size_t)row * HID + col]       = v0;
            *(float2*)&C[(size_t)(row + 8) * HID + col] = v1;
        }
    }
}

// ---- fp16 1-term kernel (V,O): plain A x B^T; stage = 2 tiles = 32KB ----
#define STAGE1_B (2 * TILE_B)
#define GEMM1_SMEM (3 * STAGE1_B)   // 98304

__global__ __launch_bounds__(256, 2)
void gemm1h(const __half* __restrict__ A, const __half* __restrict__ B,
            const float* __restrict__ bias, float* __restrict__ C)
{
    extern __shared__ char smem[];
    const uint32_t sb = smem_to_u32(smem);
    const int tid = threadIdx.x;
    const int wid = tid >> 5;
    const int lane = tid & 31;
    const int m0 = blockIdx.y << 7;
    const int n0 = blockIdx.x << 7;
    const int wm = wid >> 2;
    const int wn = wid & 3;

    const int lrow = tid >> 1;
    const int lcb  = (tid & 1) * 4;
    const uint32_t lrsw = (uint32_t)(lrow & 7) << 4;
    const __half* gsrc[2];
    gsrc[0] = A + (size_t)(m0 + lrow) * HID + lcb * 8;
    gsrc[1] = B + (size_t)(n0 + lrow) * HID + lcb * 8;
    uint32_t ldst[2][4];
#pragma unroll
    for (int t = 0; t < 2; t++)
#pragma unroll
        for (int j = 0; j < 4; j++)
            ldst[t][j] = t * TILE_B + lrow * 128 + ((uint32_t)((lcb + j) * 16) ^ lrsw);

    uint32_t a_off[4], a_sw[4];
#pragma unroll
    for (int mt = 0; mt < 4; mt++) {
        int m = wm * 64 + mt * 16 + (lane & 15);
        a_off[mt] = (uint32_t)m * 128;
        a_sw[mt]  = (uint32_t)(m & 7) << 4;
    }
    const uint32_t ka = (uint32_t)((lane >> 4) << 4);
    uint32_t b_off[2], b_sw[2];
#pragma unroll
    for (int p = 0; p < 2; p++) {
        int n = wn * 32 + p * 16 + (lane & 7) + ((lane & 16) >> 1);
        b_off[p] = (uint32_t)n * 128;
        b_sw[p]  = (uint32_t)(n & 7) << 4;
    }
    const uint32_t kb = (uint32_t)((lane & 8) << 1);

    float acc[4][4][4];
#pragma unroll
    for (int i = 0; i < 4; i++)
#pragma unroll
        for (int j = 0; j < 4; j++)
#pragma unroll
            for (int k = 0; k < 4; k++) acc[i][j][k] = 0.f;

#pragma unroll
    for (int s = 0; s < 2; s++) {
        uint32_t base = sb + s * STAGE1_B;
#pragma unroll
        for (int t = 0; t < 2; t++) {
            const __half* src = gsrc[t] + s * 64;
#pragma unroll
            for (int j = 0; j < 4; j++)
                cp16(base + ldst[t][j], src + j * 8);
        }
        CP_COMMIT();
    }

    for (int c = 0; c < 64; c++) {
        CP_WAIT1();
        __syncthreads();
        const int ldc = c + 2;
        if (ldc < 64) {
            uint32_t base = sb + (ldc % 3) * STAGE1_B;
#pragma unroll
            for (int t = 0; t < 2; t++) {
                const __half* src = gsrc[t] + ldc * 64;
#pragma unroll
                for (int j = 0; j < 4; j++)
                    cp16(base + ldst[t][j], src + j * 8);
            }
        }
        CP_COMMIT();

        const uint32_t stb = sb + (c % 3) * STAGE1_B;
#pragma unroll
        for (int ks = 0; ks < 4; ks++) {
            uint32_t af[4][4];
#pragma unroll
            for (int mt = 0; mt < 4; mt++) {
                uint32_t ko = ((uint32_t)(ks * 32) + ka) ^ a_sw[mt];
                ldsm4(af[mt], stb + a_off[mt] + ko);
            }
            uint32_t bf[2][4];
#pragma unroll
            for (int p = 0; p < 2; p++) {
                uint32_t ko = ((uint32_t)(ks * 32) + kb) ^ b_sw[p];
                ldsm4(bf[p], stb + TILE_B + b_off[p] + ko);
            }
#pragma unroll
            for (int mt = 0; mt < 4; mt++)
#pragma unroll
                for (int nt = 0; nt < 4; nt++)
                    mma_fp16(acc[mt][nt], af[mt], &bf[nt >> 1][2 * (nt & 1)]);
        }
    }

#pragma unroll
    for (int mt = 0; mt < 4; mt++) {
#pragma unroll
        for (int nt = 0; nt < 4; nt++) {
            int row = m0 + wm * 64 + mt * 16 + (lane >> 2);
            int col = n0 + wn * 32 + nt * 8 + 2 * (lane & 3);
            float2 bv = *(const float2*)&bias[col];
            float2 v0, v1;
            v0.x = acc[mt][nt][0] + bv.x; v0.y = acc[mt][nt][1] + bv.y;
            v1.x = acc[mt][nt][2] + bv.x; v1.y = acc[mt][nt][3] + bv.y;
            *(float2*)&C[(size_t)row * HID + col]       = v0;
            *(float2*)&C[(size_t)(row + 8) * HID + col] = v1;
        }
    }
}

// ============================================================================
// RoPE on packed q,k in place (angle in f32 like reference, trig in double)
// ============================================================================
__global__ void rope_kernel(const int* __restrict__ pos) {
    int idx = blockIdx.x * blockDim.x + threadIdx.x;
    if (idx >= TT * NH * 64) return;
    int i = idx & 63;
    int h = (idx >> 6) & 31;
    int t = idx >> 11;
    float p = (float)pos[t];
    float ang = p * g_freq[i];
    double ad = (double)ang;
    float c = (float)cos(ad);
    float s = (float)sin(ad);
    size_t base = ((size_t)t * NH + h) * HD;
    float x1 = g_q[base + i], x2 = g_q[base + 64 + i];
    g_q[base + i]      = x1 * c - x2 * s;
    g_q[base + 64 + i] = x2 * c + x1 * s;
    float y1 = g_k[base + i], y2 = g_k[base + 64 + i];
    g_k[base + i]      = y1 * c - y2 * s;
    g_k[base + 64 + i] = y2 * c + y1 * s;
}

// ============================================================================
// Flash attention (fp32). Epilogue writes fp16 directly into g_xh
// (input of the O GEMM) — replaces the former osplit kernel and g_o buffer.
// ============================================================================
#define ATTN_SMEM_FLOATS (8192 + 8448 + 4224 + 192)
#define ATTN_SMEM_BYTES  (ATTN_SMEM_FLOATS * 4)

__global__ __launch_bounds__(128) void attn_kernel(
    const float* __restrict__ past_k, const float* __restrict__ past_v,
    const int* __restrict__ q_start, const int* __restrict__ q_lens,
    const int* __restrict__ kv_lens, const int* __restrict__ boff)
{
    extern __shared__ float sm[];
    float* Qs   = sm;
    float* KVs  = sm + 8192;
    float* Ps   = KVs + 8448;
    float* mrow = Ps + 4224;
    float* lrow = mrow + 64;
    float* arow = lrow + 64;

    const int b = blockIdx.z, h = blockIdx.y, qt = blockIdx.x;
    const int qlen = q_lens[b];
    if (qt * 64 >= qlen) return;
    const int qs0 = q_start[b];
    const int kvlen = kv_lens[b];
    const int hist = kvlen - qlen;
    const int tid = threadIdx.x;
    const float scale = 0.08838834764831845f;
    const float NEGINF = __int_as_float(0xff800000);

    const int c4 = (tid & 31) << 2;
    const int r0 = tid >> 5;

#pragma unroll
    for (int rr = 0; rr < 16; rr++) {
        int r = r0 + rr * 4;
        int qglob = qt * 64 + r;
        float4 v = make_float4(0.f, 0.f, 0.f, 0.f);
        if (qglob < qlen)
            v = *(const float4*)&g_q[((size_t)(qs0 + qglob) * NH + h) * HD + c4];
        *(float4*)&Qs[r * 128 + c4] = v;
    }
    if (tid < 64) { mrow[tid] = NEGINF; lrow[tid] = 0.f; }
    __syncthreads();

    const int tq = tid >> 3;
    const int tk = tid & 7;

    float o[4][16];
#pragma unroll
    for (int i = 0; i < 4; i++)
#pragma unroll
        for (int j = 0; j < 16; j++) o[i][j] = 0.f;

    const int qhi  = min(qt * 64 + 63, qlen - 1);
    const int nblk = min((kvlen + 63) >> 6, ((hist + qhi) >> 6) + 1);

    for (int kb = 0; kb < nblk; kb++) {
#pragma unroll
        for (int rr = 0; rr < 16; rr++) {
            int r = r0 + rr * 4;
            int p = kb * 64 + r;
            int pc = min(p, kvlen - 1);
            const float* src;
            if (pc < hist) {
                int blk = boff[b * MAXB + (pc >> 6)];
                src = past_k + ((size_t)(blk * 64 + (pc & 63)) * NH + h) * HD;
            } else {
                src = g_k + ((size_t)(qs0 + pc - hist) * NH + h) * HD;
            }
            *(float4*)&KVs[r * 132 + c4] = *(const float4*)&src[c4];
        }
        __syncthreads();

        float s[4][8];
#pragma unroll
        for (int i = 0; i < 4; i++)
#pragma unroll
            for (int m = 0; m < 8; m++) s[i][m] = 0.f;
#pragma unroll 4
        for (int d = 0; d < 128; d += 4) {
            float4 qv[4];
#pragma unroll
            for (int i = 0; i < 4; i++)
                qv[i] = *(const float4*)&Qs[(tq * 4 + i) * 128 + d];
#pragma unroll
            for (int m = 0; m < 8; m++) {
                float4 kv = *(const float4*)&KVs[(tk + 8 * m) * 132 + d];
#pragma unroll
                for (int i = 0; i < 4; i++)
                    s[i][m] += qv[i].x * kv.x + qv[i].y * kv.y + qv[i].z * kv.z + qv[i].w * kv.w;
            }
        }
#pragma unroll
        for (int i = 0; i < 4; i++) {
            int qglob = qt * 64 + tq * 4 + i;
#pragma unroll
            for (int m = 0; m < 8; m++) {
                int kg = kb * 64 + tk + 8 * m;
                float val = (kg <= hist + qglob) ? s[i][m] * scale : NEGINF;
                Ps[(tq * 4 + i) * 66 + tk + 8 * m] = val;
            }
        }
        __syncthreads();

#pragma unroll
        for (int rr = 0; rr < 16; rr++) {
            int r = r0 + rr * 4;
            int p = kb * 64 + r;
            int pc = min(p, kvlen - 1);
            const float* src;
            if (pc < hist) {
                int blk = boff[b * MAXB + (pc >> 6)];
                src = past_v + ((size_t)(blk * 64 + (pc & 63)) * NH + h) * HD;
            } else {
                src = g_v + ((size_t)(qs0 + pc - hist) * NH + h) * HD;
            }
            *(float4*)&KVs[r * 132 + c4] = *(const float4*)&src[c4];
        }

        if (tid < 64) {
            int r = tid;
            float mo = mrow[r];
            float mx = mo;
#pragma unroll 8
            for (int j = 0; j < 64; j++) mx = fmaxf(mx, Ps[r * 66 + j]);
            float alpha = expf(mo - mx);
            float sum = 0.f;
#pragma unroll 8
            for (int j = 0; j < 64; j++) {
                float pj = expf(Ps[r * 66 + j] - mx);
                Ps[r * 66 + j] = pj;
                sum += pj;
            }
            mrow[r] = mx;
            lrow[r] = lrow[r] * alpha + sum;
            arow[r] = alpha;
        }
        __syncthreads();

#pragma unroll
        for (int i = 0; i < 4; i++) {
            float a = arow[tq * 4 + i];
#pragma unroll
            for (int j = 0; j < 16; j++) o[i][j] *= a;
        }
#pragma unroll 2
        for (int k = 0; k < 64; k++) {
            float pr[4];
#pragma unroll
            for (int i = 0; i < 4; i++) pr[i] = Ps[(tq * 4 + i) * 66 + k];
#pragma unroll
            for (int m = 0; m < 4; m++) {
                float4 vv = *(const float4*)&KVs[k * 132 + tk * 4 + 32 * m];
#pragma unroll
                for (int i = 0; i < 4; i++) {
                    o[i][m * 4 + 0] += pr[i] * vv.x;
                    o[i][m * 4 + 1] += pr[i] * vv.y;
                    o[i][m * 4 + 2] += pr[i] * vv.z;
                    o[i][m * 4 + 3] += pr[i] * vv.w;
                }
            }
        }
        __syncthreads();
    }

    // epilogue: normalize and write fp16 directly into g_xh (O-GEMM input)
#pragma unroll
    for (int i = 0; i < 4; i++) {
        int qglob = qt * 64 + tq * 4 + i;
        if (qglob >= qlen) continue;
        float inv = 1.f / lrow[tq * 4 + i];
        size_t base = ((size_t)(qs0 + qglob) * NH + h) * HD;
#pragma unroll
        for (int m = 0; m < 4; m++) {
            __half2 h0 = __half2(__float2half(o[i][m * 4 + 0] * inv),
                                 __float2half(o[i][m * 4 + 1] * inv));
            __half2 h1 = __half2(__float2half(o[i][m * 4 + 2] * inv),
                                 __float2half(o[i][m * 4 + 3] * inv));
            *(__half2*)&g_xh[base + tk * 4 + 32 * m]     = h0;
            *(__half2*)&g_xh[base + tk * 4 + 32 * m + 2] = h1;
        }
    }
}

// ============================================================================
extern "C" void kernel_launch(void* const* d_in, const int* in_sizes, int n_in,
                              void* d_out, int out_size) {
    const float* x      = (const float*)d_in[0];
    const int*   pos    = (const int*)d_in[1];
    const int*   qstart = (const int*)d_in[2];
    const int*   qlens  = (const int*)d_in[3];
    const int*   kvlens = (const int*)d_in[4];
    const int*   boff   = (const int*)d_in[5];
    const float* pk     = (const float*)d_in[6];
    const float* pv     = (const float*)d_in[7];
    const float* Wq = (const float*)d_in[8];
    const float* bq = (const float*)d_in[9];
    const float* Wk = (const float*)d_in[10];
    const float* bk = (const float*)d_in[11];
    const float* Wv = (const float*)d_in[12];
    const float* bv = (const float*)d_in[13];
    const float* Wo = (const float*)d_in[14];
    const float* bo = (const float*)d_in[15];
    float* out = (float*)d_out;

    float* vp;
    cudaGetSymbolAddress((void**)&vp, g_v);
    __nv_bfloat16 *xhi, *xlo;
    __half *xh, *w3h, *w4h;
    cudaGetSymbolAddress((void**)&xhi, g_xhi);
    cudaGetSymbolAddress((void**)&xlo, g_xlo);
    cudaGetSymbolAddress((void**)&xh,  g_xh);
    cudaGetSymbolAddress((void**)&w3h, g_w3h);
    cudaGetSymbolAddress((void**)&w4h, g_w4h);

    cudaFuncSetAttribute(gemm3qk, cudaFuncAttributeMaxDynamicSharedMemorySize, GEMM3_SMEM);
    cudaFuncSetAttribute(gemm1h,  cudaFuncAttributeMaxDynamicSharedMemorySize, GEMM1_SMEM);
    cudaFuncSetAttribute(attn_kernel, cudaFuncAttributeMaxDynamicSharedMemorySize, ATTN_SMEM_BYTES);

    const int n4x = TT * HID / 4;
    const int n4w = HID * HID / 4;
    dim3 ggqk(HID / 128, TT / 128, 2);   // (32, 24, 2) — Q and K fused
    dim3 gg(HID / 128, TT / 128);

    // 0: weight splits, 1: activation split
    wsplit_kernel<<<dim3((n4w + 255) / 256, 1, 4), 256>>>(Wq, Wk, Wv, Wo);
    xsplit3_kernel<<<(n4x + 255) / 256, 256>>>(x, n4x);
    // 2: fused Q+K GEMM (bf16 3-term, 1536 CTAs), 3: V GEMM (fp16 1-term)
    gemm3qk<<<ggqk, 256, GEMM3_SMEM>>>(xhi, xlo, bq, bk);
    gemm1h<<<gg, 256, GEMM1_SMEM>>>(xh, w3h, bv, vp);
    // 4: freq, 5: rope, 6: attention (writes fp16 g_xh directly)
    init_freq_kernel<<<1, 64>>>();
    rope_kernel<<<(TT * NH * 64 + 255) / 256, 256>>>(pos);
    attn_kernel<<<dim3(16, NH, NBAT), 128, ATTN_SMEM_BYTES>>>(pk, pv, qstart, qlens,
                                                              kvlens, boff);
    // 7: O GEMM (fp16 1-term)
    gemm1h<<<gg, 256, GEMM1_SMEM>>>(xh, w4h, bo, out);
}

// round 14
// speedup vs baseline: 1.0892x; 1.0467x over previous
#include <cuda_runtime.h>
#include <cuda_bf16.h>
#include <cuda_fp16.h>
#include <cstdint>

#define TT   3072
#define HID  4096
#define NH   32
#define HD   128
#define NBAT 4
#define MAXB 24

// ============================================================================
// helpers (baseline PTX only — no sm_103a-gated features)
// ============================================================================
__device__ __forceinline__ uint32_t smem_to_u32(const void* p) {
    uint32_t a;
    asm("{ .reg .u64 t; cvta.to.shared.u64 t, %1; cvt.u32.u64 %0, t; }" : "=r"(a) : "l"(p));
    return a;
}
__device__ __forceinline__ void cp16(uint32_t dst, const void* src) {
    asm volatile("cp.async.cg.shared.global [%0], [%1], 16;" :: "r"(dst), "l"(src));
}
#define CP_COMMIT() asm volatile("cp.async.commit_group;" ::: "memory")
#define CP_WAIT1()  asm volatile("cp.async.wait_group 1;" ::: "memory")

__device__ __forceinline__ void ldsm4(uint32_t* r, uint32_t addr) {
    asm volatile("ldmatrix.sync.aligned.m8n8.x4.shared.b16 {%0,%1,%2,%3}, [%4];"
        : "=r"(r[0]), "=r"(r[1]), "=r"(r[2]), "=r"(r[3]) : "r"(addr));
}
__device__ __forceinline__ void mma_bf16(float* c, const uint32_t* a, const uint32_t* b) {
    asm volatile("mma.sync.aligned.m16n8k16.row.col.f32.bf16.bf16.f32 "
        "{%0,%1,%2,%3}, {%4,%5,%6,%7}, {%8,%9}, {%0,%1,%2,%3};"
        : "+f"(c[0]), "+f"(c[1]), "+f"(c[2]), "+f"(c[3])
        : "r"(a[0]), "r"(a[1]), "r"(a[2]), "r"(a[3]), "r"(b[0]), "r"(b[1]));
}
__device__ __forceinline__ void mma_fp16(float* c, const uint32_t* a, const uint32_t* b) {
    asm volatile("mma.sync.aligned.m16n8k16.row.col.f32.f16.f16.f32 "
        "{%0,%1,%2,%3}, {%4,%5,%6,%7}, {%8,%9}, {%0,%1,%2,%3};"
        : "+f"(c[0]), "+f"(c[1]), "+f"(c[2]), "+f"(c[3])
        : "r"(a[0]), "r"(a[1]), "r"(a[2]), "r"(a[3]), "r"(b[0]), "r"(b[1]));
}
__device__ __forceinline__ void packsplit(float a, float b, uint32_t& hi, uint32_t& lo) {
    __half ha = __float2half(a), hb = __float2half(b);
    __half la = __float2half(a - __half2float(ha));
    __half lb = __float2half(b - __half2float(hb));
    __half2 H = __halves2half2(ha, hb), L = __halves2half2(la, lb);
    hi = *(uint32_t*)&H; lo = *(uint32_t*)&L;
}

// ---- workspace (static device arrays; no allocation) ----
__device__ float g_q[(size_t)TT * HID];
__device__ float g_k[(size_t)TT * HID];
__device__ float g_v[(size_t)TT * HID];
__device__ float g_freq[64];
__device__ __nv_bfloat16 g_xhi[(size_t)TT * HID];
__device__ __nv_bfloat16 g_xlo[(size_t)TT * HID];
__device__ __half        g_xh [(size_t)TT * HID];
__device__ __nv_bfloat16 g_w1hi[(size_t)HID * HID];
__device__ __nv_bfloat16 g_w1lo[(size_t)HID * HID];
__device__ __nv_bfloat16 g_w2hi[(size_t)HID * HID];
__device__ __nv_bfloat16 g_w2lo[(size_t)HID * HID];
__device__ __half        g_w3h [(size_t)HID * HID];
__device__ __half        g_w4h [(size_t)HID * HID];

__global__ void init_freq_kernel() {
    int i = threadIdx.x;
    if (i < 64) g_freq[i] = (float)exp(-(double)i * (log(10000.0) / 64.0));
}

// ============================================================================
// splits
// ============================================================================
__device__ __forceinline__ void split_bf16(const float* __restrict__ x,
                                           __nv_bfloat16* __restrict__ hi,
                                           __nv_bfloat16* __restrict__ lo, int i)
{
    float4 v = ((const float4*)x)[i];
    float vv[4] = {v.x, v.y, v.z, v.w};
    __nv_bfloat16 h[4], l[4];
#pragma unroll
    for (int j = 0; j < 4; j++) {
        h[j] = __float2bfloat16(vv[j]);
        l[j] = __float2bfloat16(vv[j] - __bfloat162float(h[j]));
    }
    ((__nv_bfloat162*)hi)[2 * i + 0] = __nv_bfloat162(h[0], h[1]);
    ((__nv_bfloat162*)hi)[2 * i + 1] = __nv_bfloat162(h[2], h[3]);
    ((__nv_bfloat162*)lo)[2 * i + 0] = __nv_bfloat162(l[0], l[1]);
    ((__nv_bfloat162*)lo)[2 * i + 1] = __nv_bfloat162(l[2], l[3]);
}
__device__ __forceinline__ void conv_fp16(const float* __restrict__ x,
                                          __half* __restrict__ out, int i)
{
    float4 v = ((const float4*)x)[i];
    ((__half2*)out)[2 * i + 0] = __half2(__float2half(v.x), __float2half(v.y));
    ((__half2*)out)[2 * i + 1] = __half2(__float2half(v.z), __float2half(v.w));
}

__global__ __launch_bounds__(256) void xsplit3_kernel(const float* __restrict__ x, int n4)
{
    int i = blockIdx.x * blockDim.x + threadIdx.x;
    if (i >= n4) return;
    float4 v = ((const float4*)x)[i];
    float vv[4] = {v.x, v.y, v.z, v.w};
    __nv_bfloat16 h[4], l[4];
    __half f[4];
#pragma unroll
    for (int j = 0; j < 4; j++) {
        h[j] = __float2bfloat16(vv[j]);
        l[j] = __float2bfloat16(vv[j] - __bfloat162float(h[j]));
        f[j] = __float2half(vv[j]);
    }
    ((__nv_bfloat162*)g_xhi)[2 * i + 0] = __nv_bfloat162(h[0], h[1]);
    ((__nv_bfloat162*)g_xhi)[2 * i + 1] = __nv_bfloat162(h[2], h[3]);
    ((__nv_bfloat162*)g_xlo)[2 * i + 0] = __nv_bfloat162(l[0], l[1]);
    ((__nv_bfloat162*)g_xlo)[2 * i + 1] = __nv_bfloat162(l[2], l[3]);
    ((__half2*)g_xh)[2 * i + 0] = __half2(f[0], f[1]);
    ((__half2*)g_xh)[2 * i + 1] = __half2(f[2], f[3]);
}

__global__ __launch_bounds__(256) void wsplit_kernel(
    const float* __restrict__ Wq, const float* __restrict__ Wk,
    const float* __restrict__ Wv, const float* __restrict__ Wo)
{
    int i = blockIdx.x * blockDim.x + threadIdx.x;
    const int n4 = HID * HID / 4;
    if (i >= n4) return;
    int z = blockIdx.z;
    if (z == 0)      split_bf16(Wq, g_w1hi, g_w1lo, i);
    else if (z == 1) split_bf16(Wk, g_w2hi, g_w2lo, i);
    else if (z == 2) conv_fp16(Wv, g_w3h, i);
    else             conv_fp16(Wo, g_w4h, i);
}

// ============================================================================
// GEMMs (validated R7/R9/R11 versions, unchanged)
// ============================================================================
#define TILE_B  16384
#define STAGE3_B (4 * TILE_B)
#define GEMM3_SMEM (3 * STAGE3_B)

__global__ __launch_bounds__(256)
void gemm3qk(const __nv_bfloat16* __restrict__ Ahi, const __nv_bfloat16* __restrict__ Alo,
             const float* __restrict__ bq, const float* __restrict__ bk)
{
    const int zz = blockIdx.z;
    const __nv_bfloat16* __restrict__ Bhi = zz ? g_w2hi : g_w1hi;
    const __nv_bfloat16* __restrict__ Blo = zz ? g_w2lo : g_w1lo;
    const float* __restrict__ bias = zz ? bk : bq;
    float* __restrict__ C = zz ? g_k : g_q;

    extern __shared__ char smem[];
    const uint32_t sb = smem_to_u32(smem);
    const int tid = threadIdx.x;
    const int wid = tid >> 5;
    const int lane = tid & 31;
    const int m0 = blockIdx.y << 7;
    const int n0 = blockIdx.x << 7;
    const int wm = wid >> 2;
    const int wn = wid & 3;

    const int lrow = tid >> 1;
    const int lcb  = (tid & 1) * 4;
    const uint32_t lrsw = (uint32_t)(lrow & 7) << 4;
    const __nv_bfloat16* gsrc[4];
    gsrc[0] = Ahi + (size_t)(m0 + lrow) * HID + lcb * 8;
    gsrc[1] = Alo + (size_t)(m0 + lrow) * HID + lcb * 8;
    gsrc[2] = Bhi + (size_t)(n0 + lrow) * HID + lcb * 8;
    gsrc[3] = Blo + (size_t)(n0 + lrow) * HID + lcb * 8;
    uint32_t ldst[4][4];
#pragma unroll
    for (int t = 0; t < 4; t++)
#pragma unroll
        for (int j = 0; j < 4; j++)
            ldst[t][j] = t * TILE_B + lrow * 128 + ((uint32_t)((lcb + j) * 16) ^ lrsw);

    uint32_t a_off[4], a_sw[4];
#pragma unroll
    for (int mt = 0; mt < 4; mt++) {
        int m = wm * 64 + mt * 16 + (lane & 15);
        a_off[mt] = (uint32_t)m * 128;
        a_sw[mt]  = (uint32_t)(m & 7) << 4;
    }
    const uint32_t ka = (uint32_t)((lane >> 4) << 4);
    uint32_t b_off[2], b_sw[2];
#pragma unroll
    for (int p = 0; p < 2; p++) {
        int n = wn * 32 + p * 16 + (lane & 7) + ((lane & 16) >> 1);
        b_off[p] = (uint32_t)n * 128;
        b_sw[p]  = (uint32_t)(n & 7) << 4;
    }
    const uint32_t kb = (uint32_t)((lane & 8) << 1);

    float acc[4][4][4];
#pragma unroll
    for (int i = 0; i < 4; i++)
#pragma unroll
        for (int j = 0; j < 4; j++)
#pragma unroll
            for (int k = 0; k < 4; k++) acc[i][j][k] = 0.f;

#pragma unroll
    for (int s = 0; s < 2; s++) {
        uint32_t base = sb + s * STAGE3_B;
#pragma unroll
        for (int t = 0; t < 4; t++) {
            const __nv_bfloat16* src = gsrc[t] + s * 64;
#pragma unroll
            for (int j = 0; j < 4; j++)
                cp16(base + ldst[t][j], src + j * 8);
        }
        CP_COMMIT();
    }

    for (int c = 0; c < 64; c++) {
        CP_WAIT1();
        __syncthreads();
        const int ldc = c + 2;
        if (ldc < 64) {
            uint32_t base = sb + (ldc % 3) * STAGE3_B;
#pragma unroll
            for (int t = 0; t < 4; t++) {
                const __nv_bfloat16* src = gsrc[t] + ldc * 64;
#pragma unroll
                for (int j = 0; j < 4; j++)
                    cp16(base + ldst[t][j], src + j * 8);
            }
        }
        CP_COMMIT();

        const uint32_t stb = sb + (c % 3) * STAGE3_B;
#pragma unroll
        for (int ks = 0; ks < 4; ks++) {
            uint32_t ahi[4][4], alo[4][4];
#pragma unroll
            for (int mt = 0; mt < 4; mt++) {
                uint32_t ko = ((uint32_t)(ks * 32) + ka) ^ a_sw[mt];
                uint32_t ad = stb + a_off[mt] + ko;
                ldsm4(ahi[mt], ad);
                ldsm4(alo[mt], ad + TILE_B);
            }
            uint32_t bhi[2][4], blo[2][4];
#pragma unroll
            for (int p = 0; p < 2; p++) {
                uint32_t ko = ((uint32_t)(ks * 32) + kb) ^ b_sw[p];
                uint32_t bd = stb + 2 * TILE_B + b_off[p] + ko;
                ldsm4(bhi[p], bd);
                ldsm4(blo[p], bd + TILE_B);
            }
#pragma unroll
            for (int mt = 0; mt < 4; mt++)
#pragma unroll
                for (int nt = 0; nt < 4; nt++) {
                    const uint32_t* bh = &bhi[nt >> 1][2 * (nt & 1)];
                    const uint32_t* bl = &blo[nt >> 1][2 * (nt & 1)];
                    mma_bf16(acc[mt][nt], ahi[mt], bh);
                    mma_bf16(acc[mt][nt], ahi[mt], bl);
                    mma_bf16(acc[mt][nt], alo[mt], bh);
                }
        }
    }

#pragma unroll
    for (int mt = 0; mt < 4; mt++) {
#pragma unroll
        for (int nt = 0; nt < 4; nt++) {
            int row = m0 + wm * 64 + mt * 16 + (lane >> 2);
            int col = n0 + wn * 32 + nt * 8 + 2 * (lane & 3);
            float2 bv = *(const float2*)&bias[col];
            float2 v0, v1;
            v0.x = acc[mt][nt][0] + bv.x; v0.y = acc[mt][nt][1] + bv.y;
            v1.x = acc[mt][nt][2] + bv.x; v1.y = acc[mt][nt][3] + bv.y;
            *(float2*)&C[(size_t)row * HID + col]       = v0;
            *(float2*)&C[(size_t)(row + 8) * HID + col] = v1;
        }
    }
}

#define STAGE1_B (2 * TILE_B)
#define GEMM1_SMEM (3 * STAGE1_B)

__global__ __launch_bounds__(256, 2)
void gemm1h(const __half* __restrict__ A, const __half* __restrict__ B,
            const float* __restrict__ bias, float* __restrict__ C)
{
    extern __shared__ char smem[];
    const uint32_t sb = smem_to_u32(smem);
    const int tid = threadIdx.x;
    const int wid = tid >> 5;
    const int lane = tid & 31;
    const int m0 = blockIdx.y << 7;
    const int n0 = blockIdx.x << 7;
    const int wm = wid >> 2;
    const int wn = wid & 3;

    const int lrow = tid >> 1;
    const int lcb  = (tid & 1) * 4;
    const uint32_t lrsw = (uint32_t)(lrow & 7) << 4;
    const __half* gsrc[2];
    gsrc[0] = A + (size_t)(m0 + lrow) * HID + lcb * 8;
    gsrc[1] = B + (size_t)(n0 + lrow) * HID + lcb * 8;
    uint32_t ldst[2][4];
#pragma unroll
    for (int t = 0; t < 2; t++)
#pragma unroll
        for (int j = 0; j < 4; j++)
            ldst[t][j] = t * TILE_B + lrow * 128 + ((uint32_t)((lcb + j) * 16) ^ lrsw);

    uint32_t a_off[4], a_sw[4];
#pragma unroll
    for (int mt = 0; mt < 4; mt++) {
        int m = wm * 64 + mt * 16 + (lane & 15);
        a_off[mt] = (uint32_t)m * 128;
        a_sw[mt]  = (uint32_t)(m & 7) << 4;
    }
    const uint32_t ka = (uint32_t)((lane >> 4) << 4);
    uint32_t b_off[2], b_sw[2];
#pragma unroll
    for (int p = 0; p < 2; p++) {
        int n = wn * 32 + p * 16 + (lane & 7) + ((lane & 16) >> 1);
        b_off[p] = (uint32_t)n * 128;
        b_sw[p]  = (uint32_t)(n & 7) << 4;
    }
    const uint32_t kb = (uint32_t)((lane & 8) << 1);

    float acc[4][4][4];
#pragma unroll
    for (int i = 0; i < 4; i++)
#pragma unroll
        for (int j = 0; j < 4; j++)
#pragma unroll
            for (int k = 0; k < 4; k++) acc[i][j][k] = 0.f;

#pragma unroll
    for (int s = 0; s < 2; s++) {
        uint32_t base = sb + s * STAGE1_B;
#pragma unroll
        for (int t = 0; t < 2; t++) {
            const __half* src = gsrc[t] + s * 64;
#pragma unroll
            for (int j = 0; j < 4; j++)
                cp16(base + ldst[t][j], src + j * 8);
        }
        CP_COMMIT();
    }

    for (int c = 0; c < 64; c++) {
        CP_WAIT1();
        __syncthreads();
        const int ldc = c + 2;
        if (ldc < 64) {
            uint32_t base = sb + (ldc % 3) * STAGE1_B;
#pragma unroll
            for (int t = 0; t < 2; t++) {
                const __half* src = gsrc[t] + ldc * 64;
#pragma unroll
                for (int j = 0; j < 4; j++)
                    cp16(base + ldst[t][j], src + j * 8);
            }
        }
        CP_COMMIT();

        const uint32_t stb = sb + (c % 3) * STAGE1_B;
#pragma unroll
        for (int ks = 0; ks < 4; ks++) {
            uint32_t af[4][4];
#pragma unroll
            for (int mt = 0; mt < 4; mt++) {
                uint32_t ko = ((uint32_t)(ks * 32) + ka) ^ a_sw[mt];
                ldsm4(af[mt], stb + a_off[mt] + ko);
            }
            uint32_t bf[2][4];
#pragma unroll
            for (int p = 0; p < 2; p++) {
                uint32_t ko = ((uint32_t)(ks * 32) + kb) ^ b_sw[p];
                ldsm4(bf[p], stb + TILE_B + b_off[p] + ko);
            }
#pragma unroll
            for (int mt = 0; mt < 4; mt++)
#pragma unroll
                for (int nt = 0; nt < 4; nt++)
                    mma_fp16(acc[mt][nt], af[mt], &bf[nt >> 1][2 * (nt & 1)]);
        }
    }

#pragma unroll
    for (int mt = 0; mt < 4; mt++) {
#pragma unroll
        for (int nt = 0; nt < 4; nt++) {
            int row = m0 + wm * 64 + mt * 16 + (lane >> 2);
            int col = n0 + wn * 32 + nt * 8 + 2 * (lane & 3);
            float2 bv = *(const float2*)&bias[col];
            float2 v0, v1;
            v0.x = acc[mt][nt][0] + bv.x; v0.y = acc[mt][nt][1] + bv.y;
            v1.x = acc[mt][nt][2] + bv.x; v1.y = acc[mt][nt][3] + bv.y;
            *(float2*)&C[(size_t)row * HID + col]       = v0;
            *(float2*)&C[(size_t)(row + 8) * HID + col] = v1;
        }
    }
}

// ============================================================================
// RoPE (unchanged)
// ============================================================================
__global__ void rope_kernel(const int* __restrict__ pos) {
    int idx = blockIdx.x * blockDim.x + threadIdx.x;
    if (idx >= TT * NH * 64) return;
    int i = idx & 63;
    int h = (idx >> 6) & 31;
    int t = idx >> 11;
    float p = (float)pos[t];
    float ang = p * g_freq[i];
    double ad = (double)ang;
    float c = (float)cos(ad);
    float s = (float)sin(ad);
    size_t base = ((size_t)t * NH + h) * HD;
    float x1 = g_q[base + i], x2 = g_q[base + 64 + i];
    g_q[base + i]      = x1 * c - x2 * s;
    g_q[base + 64 + i] = x2 * c + x1 * s;
    float y1 = g_k[base + i], y2 = g_k[base + 64 + i];
    g_k[base + i]      = y1 * c - y2 * s;
    g_k[base + 64 + i] = y2 * c + y1 * s;
}

// ============================================================================
// Tensor-core flash attention (fp16 hi/lo 3-term for QK^T and P.V).
// CTA = (64 q-rows, head, batch), 4 warps x 16 rows. Q frags in registers
// (scale folded). K smem [64][136] halves (hi/lo); V^T smem [128][74] (hi/lo).
// Epilogue writes fp16 g_xh directly (O-GEMM input).
// ============================================================================
#define KPAD 136
#define VPAD 74
#define SM_KH 0
#define SM_KL (64 * KPAD)
#define SM_VH (2 * 64 * KPAD)
#define SM_VL (2 * 64 * KPAD + 128 * VPAD)
#define ATTN_SMEM_HALVES (2 * 64 * KPAD + 2 * 128 * VPAD)
#define ATTN_SMEM_BYTES  (ATTN_SMEM_HALVES * 2)   // 72704

__global__ __launch_bounds__(128) void attn_kernel(
    const float* __restrict__ past_k, const float* __restrict__ past_v,
    const int* __restrict__ q_start, const int* __restrict__ q_lens,
    const int* __restrict__ kv_lens, const int* __restrict__ boff)
{
    extern __shared__ __half sh[];
    __half* sKh = sh + SM_KH;
    __half* sKl = sh + SM_KL;
    __half* sVh = sh + SM_VH;
    __half* sVl = sh + SM_VL;

    const int b = blockIdx.z, h = blockIdx.y, qt = blockIdx.x;
    const int qlen = q_lens[b];
    if (qt * 64 >= qlen) return;
    const int qs0 = q_start[b];
    const int kvlen = kv_lens[b];
    const int hist = kvlen - qlen;
    const int tid = threadIdx.x;
    const int wrp = tid >> 5;
    const int lane = tid & 31;
    const float scale = 0.08838834764831845f;

    const int lq = lane >> 2;          // 0..7 (row within m16 half)
    const int lc = (lane & 3) * 2;     // col-pair base

    // ---- Q fragments (A-operand, m16k16 x 8 k-steps), scale folded, hi/lo ----
    const int ra_g = qt * 64 + wrp * 16 + lq;
    const int rb_g = ra_g + 8;
    const float* qrowa = g_q + ((size_t)(qs0 + min(ra_g, qlen - 1)) * NH + h) * HD;
    const float* qrowb = g_q + ((size_t)(qs0 + min(rb_g, qlen - 1)) * NH + h) * HD;
    const bool va_ok = ra_g < qlen, vb_ok = rb_g < qlen;

    uint32_t qhf[8][4], qlf[8][4];
#pragma unroll
    for (int ks = 0; ks < 8; ks++) {
        int k0 = ks * 16 + lc;
        float2 a0 = va_ok ? *(const float2*)&qrowa[k0]     : make_float2(0.f, 0.f);
        float2 a2 = va_ok ? *(const float2*)&qrowa[k0 + 8] : make_float2(0.f, 0.f);
        float2 a1 = vb_ok ? *(const float2*)&qrowb[k0]     : make_float2(0.f, 0.f);
        float2 a3 = vb_ok ? *(const float2*)&qrowb[k0 + 8] : make_float2(0.f, 0.f);
        packsplit(a0.x * scale, a0.y * scale, qhf[ks][0], qlf[ks][0]);
        packsplit(a1.x * scale, a1.y * scale, qhf[ks][1], qlf[ks][1]);
        packsplit(a2.x * scale, a2.y * scale, qhf[ks][2], qlf[ks][2]);
        packsplit(a3.x * scale, a3.y * scale, qhf[ks][3], qlf[ks][3]);
    }

    float o[16][4];
#pragma unroll
    for (int i = 0; i < 16; i++)
#pragma unroll
        for (int j = 0; j < 4; j++) o[i][j] = 0.f;
    float ma = -1e30f, mb = -1e30f, la = 0.f, lb = 0.f;

    const int qhi  = min(qt * 64 + 63, qlen - 1);
    const int nblk = min((kvlen + 63) >> 6, ((hist + qhi) >> 6) + 1);

    const int kr0 = tid >> 5;           // K-fill base row
    const int kc4 = (tid & 31) * 4;     // K-fill dim offset

    for (int kb = 0; kb < nblk; kb++) {
        // ---- fill K (hi/lo) ----
#pragma unroll
        for (int rr = 0; rr < 16; rr++) {
            int r = kr0 + rr * 4;
            int p = kb * 64 + r;
            int pc = min(p, kvlen - 1);
            const float* src;
            if (pc < hist) {
                int blk = boff[b * MAXB + (pc >> 6)];
                src = past_k + ((size_t)(blk * 64 + (pc & 63)) * NH + h) * HD;
            } else {
                src = g_k + ((size_t)(qs0 + pc - hist) * NH + h) * HD;
            }
            float4 v = *(const float4*)&src[kc4];
            float vv[4] = {v.x, v.y, v.z, v.w};
#pragma unroll
            for (int j = 0; j < 4; j++) {
                __half hh = __float2half(vv[j]);
                sKh[r * KPAD + kc4 + j] = hh;
                sKl[r * KPAD + kc4 + j] = __float2half(vv[j] - __half2float(hh));
            }
        }
        // ---- fill V transposed (hi/lo): thread = dim, iterate keys ----
        for (int kk = 0; kk < 64; kk++) {
            int p = kb * 64 + kk;
            int pc = min(p, kvlen - 1);
            const float* src;
            if (pc < hist) {
                int blk = boff[b * MAXB + (pc >> 6)];
                src = past_v + ((size_t)(blk * 64 + (pc & 63)) * NH + h) * HD;
            } else {
                src = g_v + ((size_t)(qs0 + pc - hist) * NH + h) * HD;
            }
            float v = src[tid];
            __half hh = __float2half(v);
            sVh[tid * VPAD + kk] = hh;
            sVl[tid * VPAD + kk] = __float2half(v - __half2float(hh));
        }
        __syncthreads();

        // ---- S = Q K^T (3-term fp16) ----
        float s[8][4];
#pragma unroll
        for (int nt = 0; nt < 8; nt++)
#pragma unroll
            for (int j = 0; j < 4; j++) s[nt][j] = 0.f;
#pragma unroll
        for (int ks = 0; ks < 8; ks++) {
#pragma unroll
            for (int nt = 0; nt < 8; nt++) {
                const __half* kh = &sKh[(nt * 8 + lq) * KPAD + ks * 16 + lc];
                const __half* kl = &sKl[(nt * 8 + lq) * KPAD + ks * 16 + lc];
                uint32_t bh[2] = {*(const uint32_t*)kh, *(const uint32_t*)(kh + 8)};
                uint32_t bl[2] = {*(const uint32_t*)kl, *(const uint32_t*)(kl + 8)};
                mma_fp16(s[nt], qhf[ks], bh);
                mma_fp16(s[nt], qhf[ks], bl);
                mma_fp16(s[nt], qlf[ks], bh);
            }
        }

        // ---- mask + online softmax (fp32) ----
        float mxa = -1e30f, mxb = -1e30f;
#pragma unroll
        for (int nt = 0; nt < 8; nt++) {
            int kg = kb * 64 + nt * 8 + lc;
            s[nt][0] = (kg     <= hist + ra_g) ? s[nt][0] : -1e30f;
            s[nt][1] = (kg + 1 <= hist + ra_g) ? s[nt][1] : -1e30f;
            s[nt][2] = (kg     <= hist + rb_g) ? s[nt][2] : -1e30f;
            s[nt][3] = (kg + 1 <= hist + rb_g) ? s[nt][3] : -1e30f;
            mxa = fmaxf(mxa, fmaxf(s[nt][0], s[nt][1]));
            mxb = fmaxf(mxb, fmaxf(s[nt][2], s[nt][3]));
        }
        mxa = fmaxf(mxa, __shfl_xor_sync(0xffffffffu, mxa, 1));
        mxa = fmaxf(mxa, __shfl_xor_sync(0xffffffffu, mxa, 2));
        mxb = fmaxf(mxb, __shfl_xor_sync(0xffffffffu, mxb, 1));
        mxb = fmaxf(mxb, __shfl_xor_sync(0xffffffffu, mxb, 2));

        float mna = fmaxf(ma, mxa), mnb = fmaxf(mb, mxb);
        float alpha_a = __expf(ma - mna), alpha_b = __expf(mb - mnb);
        ma = mna; mb = mnb;

        float suma = 0.f, sumb = 0.f;
#pragma unroll
        for (int nt = 0; nt < 8; nt++) {
            s[nt][0] = __expf(s[nt][0] - ma);
            s[nt][1] = __expf(s[nt][1] - ma);
            s[nt][2] = __expf(s[nt][2] - mb);
            s[nt][3] = __expf(s[nt][3] - mb);
            suma += s[nt][0] + s[nt][1];
            sumb += s[nt][2] + s[nt][3];
        }
        suma += __shfl_xor_sync(0xffffffffu, suma, 1);
        suma += __shfl_xor_sync(0xffffffffu, suma, 2);
        sumb += __shfl_xor_sync(0xffffffffu, sumb, 1);
        sumb += __shfl_xor_sync(0xffffffffu, sumb, 2);
        la = la * alpha_a + suma;
        lb = lb * alpha_b + sumb;

#pragma unroll
        for (int dt = 0; dt < 16; dt++) {
            o[dt][0] *= alpha_a; o[dt][1] *= alpha_a;
            o[dt][2] *= alpha_b; o[dt][3] *= alpha_b;
        }

        // ---- O += P V (3-term fp16); P frags from S accum layout ----
#pragma unroll
        for (int t = 0; t < 4; t++) {
            uint32_t ph[4], pl[4];
            packsplit(s[2 * t][0],     s[2 * t][1],     ph[0], pl[0]);
            packsplit(s[2 * t][2],     s[2 * t][3],     ph[1], pl[1]);
            packsplit(s[2 * t + 1][0], s[2 * t + 1][1], ph[2], pl[2]);
            packsplit(s[2 * t + 1][2], s[2 * t + 1][3], ph[3], pl[3]);
#pragma unroll
            for (int dt = 0; dt < 16; dt++) {
                const __half* vh = &sVh[(dt * 8 + lq) * VPAD + t * 16 + lc];
                const __half* vl = &sVl[(dt * 8 + lq) * VPAD + t * 16 + lc];
                uint32_t bh[2] = {*(const uint32_t*)vh, *(const uint32_t*)(vh + 8)};
                uint32_t bl[2] = {*(const uint32_t*)vl, *(const uint32_t*)(vl + 8)};
                mma_fp16(o[dt], ph, bh);
                mma_fp16(o[dt], ph, bl);
                mma_fp16(o[dt], pl, bh);
            }
        }
        __syncthreads();
    }

    // ---- epilogue: normalize, write fp16 to g_xh ----
    float inva = 1.f / la, invb = 1.f / lb;
    __half* outa = g_xh + ((size_t)(qs0 + ra_g) * NH + h) * HD;
    __half* outb = g_xh + ((size_t)(qs0 + rb_g) * NH + h) * HD;
#pragma unroll
    for (int dt = 0; dt < 16; dt++) {
        int d0 = dt * 8 + lc;
        if (va_ok) {
            __half2 w = __halves2half2(__float2half(o[dt][0] * inva),
                                       __float2half(o[dt][1] * inva));
            *(__half2*)&outa[d0] = w;
        }
        if (vb_ok) {
            __half2 w = __halves2half2(__float2half(o[dt][2] * invb),
                                       __float2half(o[dt][3] * invb));
            *(__half2*)&outb[d0] = w;
        }
    }
}

// ============================================================================
extern "C" void kernel_launch(void* const* d_in, const int* in_sizes, int n_in,
                              void* d_out, int out_size) {
    const float* x      = (const float*)d_in[0];
    const int*   pos    = (const int*)d_in[1];
    const int*   qstart = (const int*)d_in[2];
    const int*   qlens  = (const int*)d_in[3];
    const int*   kvlens = (const int*)d_in[4];
    const int*   boff   = (const int*)d_in[5];
    const float* pk     = (const float*)d_in[6];
    const float* pv     = (const float*)d_in[7];
    const float* Wq = (const float*)d_in[8];
    const float* bq = (const float*)d_in[9];
    const float* Wk = (const float*)d_in[10];
    const float* bk = (const float*)d_in[11];
    const float* Wv = (const float*)d_in[12];
    const float* bv = (const float*)d_in[13];
    const float* Wo = (const float*)d_in[14];
    const float* bo = (const float*)d_in[15];
    float* out = (float*)d_out;

    float* vp;
    cudaGetSymbolAddress((void**)&vp, g_v);
    __nv_bfloat16 *xhi, *xlo;
    __half *xh, *w3h, *w4h;
    cudaGetSymbolAddress((void**)&xhi, g_xhi);
    cudaGetSymbolAddress((void**)&xlo, g_xlo);
    cudaGetSymbolAddress((void**)&xh,  g_xh);
    cudaGetSymbolAddress((void**)&w3h, g_w3h);
    cudaGetSymbolAddress((void**)&w4h, g_w4h);

    cudaFuncSetAttribute(gemm3qk, cudaFuncAttributeMaxDynamicSharedMemorySize, GEMM3_SMEM);
    cudaFuncSetAttribute(gemm1h,  cudaFuncAttributeMaxDynamicSharedMemorySize, GEMM1_SMEM);
    cudaFuncSetAttribute(attn_kernel, cudaFuncAttributeMaxDynamicSharedMemorySize, ATTN_SMEM_BYTES);

    const int n4x = TT * HID / 4;
    const int n4w = HID * HID / 4;
    dim3 ggqk(HID / 128, TT / 128, 2);
    dim3 gg(HID / 128, TT / 128);

    wsplit_kernel<<<dim3((n4w + 255) / 256, 1, 4), 256>>>(Wq, Wk, Wv, Wo);
    xsplit3_kernel<<<(n4x + 255) / 256, 256>>>(x, n4x);
    gemm3qk<<<ggqk, 256, GEMM3_SMEM>>>(xhi, xlo, bq, bk);
    gemm1h<<<gg, 256, GEMM1_SMEM>>>(xh, w3h, bv, vp);
    init_freq_kernel<<<1, 64>>>();
    rope_kernel<<<(TT * NH * 64 + 255) / 256, 256>>>(pos);
    attn_kernel<<<dim3(16, NH, NBAT), 128, ATTN_SMEM_BYTES>>>(pk, pv, qstart, qlens,
                                                              kvlens, boff);
    gemm1h<<<gg, 256, GEMM1_SMEM>>>(xh, w4h, bo, out);
}

// round 15
// speedup vs baseline: 1.1123x; 1.0213x over previous
#include <cuda_runtime.h>
#include <cuda_bf16.h>
#include <cuda_fp16.h>
#include <cstdint>

#define TT   3072
#define HID  4096
#define NH   32
#define HD   128
#define NBAT 4
#define MAXB 24

// ============================================================================
// helpers (baseline PTX only — no sm_103a-gated features)
// ============================================================================
__device__ __forceinline__ uint32_t smem_to_u32(const void* p) {
    uint32_t a;
    asm("{ .reg .u64 t; cvta.to.shared.u64 t, %1; cvt.u32.u64 %0, t; }" : "=r"(a) : "l"(p));
    return a;
}
__device__ __forceinline__ void cp16(uint32_t dst, const void* src) {
    asm volatile("cp.async.cg.shared.global [%0], [%1], 16;" :: "r"(dst), "l"(src));
}
#define CP_COMMIT() asm volatile("cp.async.commit_group;" ::: "memory")
#define CP_WAIT1()  asm volatile("cp.async.wait_group 1;" ::: "memory")

__device__ __forceinline__ void ldsm4(uint32_t* r, uint32_t addr) {
    asm volatile("ldmatrix.sync.aligned.m8n8.x4.shared.b16 {%0,%1,%2,%3}, [%4];"
        : "=r"(r[0]), "=r"(r[1]), "=r"(r[2]), "=r"(r[3]) : "r"(addr));
}
__device__ __forceinline__ void mma_bf16(float* c, const uint32_t* a, const uint32_t* b) {
    asm volatile("mma.sync.aligned.m16n8k16.row.col.f32.bf16.bf16.f32 "
        "{%0,%1,%2,%3}, {%4,%5,%6,%7}, {%8,%9}, {%0,%1,%2,%3};"
        : "+f"(c[0]), "+f"(c[1]), "+f"(c[2]), "+f"(c[3])
        : "r"(a[0]), "r"(a[1]), "r"(a[2]), "r"(a[3]), "r"(b[0]), "r"(b[1]));
}
__device__ __forceinline__ void mma_fp16(float* c, const uint32_t* a, const uint32_t* b) {
    asm volatile("mma.sync.aligned.m16n8k16.row.col.f32.f16.f16.f32 "
        "{%0,%1,%2,%3}, {%4,%5,%6,%7}, {%8,%9}, {%0,%1,%2,%3};"
        : "+f"(c[0]), "+f"(c[1]), "+f"(c[2]), "+f"(c[3])
        : "r"(a[0]), "r"(a[1]), "r"(a[2]), "r"(a[3]), "r"(b[0]), "r"(b[1]));
}
__device__ __forceinline__ void packsplit(float a, float b, uint32_t& hi, uint32_t& lo) {
    __half ha = __float2half(a), hb = __float2half(b);
    __half la = __float2half(a - __half2float(ha));
    __half lb = __float2half(b - __half2float(hb));
    __half2 H = __halves2half2(ha, hb), L = __halves2half2(la, lb);
    hi = *(uint32_t*)&H; lo = *(uint32_t*)&L;
}
__device__ __forceinline__ uint32_t packh2(float a, float b) {
    __half2 H = __halves2half2(__float2half(a), __float2half(b));
    return *(uint32_t*)&H;
}

// ---- workspace (static device arrays; no allocation) ----
__device__ float g_q[(size_t)TT * HID];
__device__ float g_k[(size_t)TT * HID];
__device__ float g_v[(size_t)TT * HID];
__device__ float g_freq[64];
__device__ __nv_bfloat16 g_xhi[(size_t)TT * HID];
__device__ __nv_bfloat16 g_xlo[(size_t)TT * HID];
__device__ __half        g_xh [(size_t)TT * HID];
__device__ __nv_bfloat16 g_w1hi[(size_t)HID * HID];
__device__ __nv_bfloat16 g_w1lo[(size_t)HID * HID];
__device__ __nv_bfloat16 g_w2hi[(size_t)HID * HID];
__device__ __nv_bfloat16 g_w2lo[(size_t)HID * HID];
__device__ __half        g_w3h [(size_t)HID * HID];
__device__ __half        g_w4h [(size_t)HID * HID];

__global__ void init_freq_kernel() {
    int i = threadIdx.x;
    if (i < 64) g_freq[i] = (float)exp(-(double)i * (log(10000.0) / 64.0));
}

// ============================================================================
// splits
// ============================================================================
__device__ __forceinline__ void split_bf16(const float* __restrict__ x,
                                           __nv_bfloat16* __restrict__ hi,
                                           __nv_bfloat16* __restrict__ lo, int i)
{
    float4 v = ((const float4*)x)[i];
    float vv[4] = {v.x, v.y, v.z, v.w};
    __nv_bfloat16 h[4], l[4];
#pragma unroll
    for (int j = 0; j < 4; j++) {
        h[j] = __float2bfloat16(vv[j]);
        l[j] = __float2bfloat16(vv[j] - __bfloat162float(h[j]));
    }
    ((__nv_bfloat162*)hi)[2 * i + 0] = __nv_bfloat162(h[0], h[1]);
    ((__nv_bfloat162*)hi)[2 * i + 1] = __nv_bfloat162(h[2], h[3]);
    ((__nv_bfloat162*)lo)[2 * i + 0] = __nv_bfloat162(l[0], l[1]);
    ((__nv_bfloat162*)lo)[2 * i + 1] = __nv_bfloat162(l[2], l[3]);
}
__device__ __forceinline__ void conv_fp16(const float* __restrict__ x,
                                          __half* __restrict__ out, int i)
{
    float4 v = ((const float4*)x)[i];
    ((__half2*)out)[2 * i + 0] = __half2(__float2half(v.x), __float2half(v.y));
    ((__half2*)out)[2 * i + 1] = __half2(__float2half(v.z), __float2half(v.w));
}

__global__ __launch_bounds__(256) void xsplit3_kernel(const float* __restrict__ x, int n4)
{
    int i = blockIdx.x * blockDim.x + threadIdx.x;
    if (i >= n4) return;
    float4 v = ((const float4*)x)[i];
    float vv[4] = {v.x, v.y, v.z, v.w};
    __nv_bfloat16 h[4], l[4];
    __half f[4];
#pragma unroll
    for (int j = 0; j < 4; j++) {
        h[j] = __float2bfloat16(vv[j]);
        l[j] = __float2bfloat16(vv[j] - __bfloat162float(h[j]));
        f[j] = __float2half(vv[j]);
    }
    ((__nv_bfloat162*)g_xhi)[2 * i + 0] = __nv_bfloat162(h[0], h[1]);
    ((__nv_bfloat162*)g_xhi)[2 * i + 1] = __nv_bfloat162(h[2], h[3]);
    ((__nv_bfloat162*)g_xlo)[2 * i + 0] = __nv_bfloat162(l[0], l[1]);
    ((__nv_bfloat162*)g_xlo)[2 * i + 1] = __nv_bfloat162(l[2], l[3]);
    ((__half2*)g_xh)[2 * i + 0] = __half2(f[0], f[1]);
    ((__half2*)g_xh)[2 * i + 1] = __half2(f[2], f[3]);
}

__global__ __launch_bounds__(256) void wsplit_kernel(
    const float* __restrict__ Wq, const float* __restrict__ Wk,
    const float* __restrict__ Wv, const float* __restrict__ Wo)
{
    int i = blockIdx.x * blockDim.x + threadIdx.x;
    const int n4 = HID * HID / 4;
    if (i >= n4) return;
    int z = blockIdx.z;
    if (z == 0)      split_bf16(Wq, g_w1hi, g_w1lo, i);
    else if (z == 1) split_bf16(Wk, g_w2hi, g_w2lo, i);
    else if (z == 2) conv_fp16(Wv, g_w3h, i);
    else             conv_fp16(Wo, g_w4h, i);
}

// ============================================================================
// GEMMs (validated, unchanged)
// ============================================================================
#define TILE_B  16384
#define STAGE3_B (4 * TILE_B)
#define GEMM3_SMEM (3 * STAGE3_B)

__global__ __launch_bounds__(256)
void gemm3qk(const __nv_bfloat16* __restrict__ Ahi, const __nv_bfloat16* __restrict__ Alo,
             const float* __restrict__ bq, const float* __restrict__ bk)
{
    const int zz = blockIdx.z;
    const __nv_bfloat16* __restrict__ Bhi = zz ? g_w2hi : g_w1hi;
    const __nv_bfloat16* __restrict__ Blo = zz ? g_w2lo : g_w1lo;
    const float* __restrict__ bias = zz ? bk : bq;
    float* __restrict__ C = zz ? g_k : g_q;

    extern __shared__ char smem[];
    const uint32_t sb = smem_to_u32(smem);
    const int tid = threadIdx.x;
    const int wid = tid >> 5;
    const int lane = tid & 31;
    const int m0 = blockIdx.y << 7;
    const int n0 = blockIdx.x << 7;
    const int wm = wid >> 2;
    const int wn = wid & 3;

    const int lrow = tid >> 1;
    const int lcb  = (tid & 1) * 4;
    const uint32_t lrsw = (uint32_t)(lrow & 7) << 4;
    const __nv_bfloat16* gsrc[4];
    gsrc[0] = Ahi + (size_t)(m0 + lrow) * HID + lcb * 8;
    gsrc[1] = Alo + (size_t)(m0 + lrow) * HID + lcb * 8;
    gsrc[2] = Bhi + (size_t)(n0 + lrow) * HID + lcb * 8;
    gsrc[3] = Blo + (size_t)(n0 + lrow) * HID + lcb * 8;
    uint32_t ldst[4][4];
#pragma unroll
    for (int t = 0; t < 4; t++)
#pragma unroll
        for (int j = 0; j < 4; j++)
            ldst[t][j] = t * TILE_B + lrow * 128 + ((uint32_t)((lcb + j) * 16) ^ lrsw);

    uint32_t a_off[4], a_sw[4];
#pragma unroll
    for (int mt = 0; mt < 4; mt++) {
        int m = wm * 64 + mt * 16 + (lane & 15);
        a_off[mt] = (uint32_t)m * 128;
        a_sw[mt]  = (uint32_t)(m & 7) << 4;
    }
    const uint32_t ka = (uint32_t)((lane >> 4) << 4);
    uint32_t b_off[2], b_sw[2];
#pragma unroll
    for (int p = 0; p < 2; p++) {
        int n = wn * 32 + p * 16 + (lane & 7) + ((lane & 16) >> 1);
        b_off[p] = (uint32_t)n * 128;
        b_sw[p]  = (uint32_t)(n & 7) << 4;
    }
    const uint32_t kb = (uint32_t)((lane & 8) << 1);

    float acc[4][4][4];
#pragma unroll
    for (int i = 0; i < 4; i++)
#pragma unroll
        for (int j = 0; j < 4; j++)
#pragma unroll
            for (int k = 0; k < 4; k++) acc[i][j][k] = 0.f;

#pragma unroll
    for (int s = 0; s < 2; s++) {
        uint32_t base = sb + s * STAGE3_B;
#pragma unroll
        for (int t = 0; t < 4; t++) {
            const __nv_bfloat16* src = gsrc[t] + s * 64;
#pragma unroll
            for (int j = 0; j < 4; j++)
                cp16(base + ldst[t][j], src + j * 8);
        }
        CP_COMMIT();
    }

    for (int c = 0; c < 64; c++) {
        CP_WAIT1();
        __syncthreads();
        const int ldc = c + 2;
        if (ldc < 64) {
            uint32_t base = sb + (ldc % 3) * STAGE3_B;
#pragma unroll
            for (int t = 0; t < 4; t++) {
                const __nv_bfloat16* src = gsrc[t] + ldc * 64;
#pragma unroll
                for (int j = 0; j < 4; j++)
                    cp16(base + ldst[t][j], src + j * 8);
            }
        }
        CP_COMMIT();

        const uint32_t stb = sb + (c % 3) * STAGE3_B;
#pragma unroll
        for (int ks = 0; ks < 4; ks++) {
            uint32_t ahi[4][4], alo[4][4];
#pragma unroll
            for (int mt = 0; mt < 4; mt++) {
                uint32_t ko = ((uint32_t)(ks * 32) + ka) ^ a_sw[mt];
                uint32_t ad = stb + a_off[mt] + ko;
                ldsm4(ahi[mt], ad);
                ldsm4(alo[mt], ad + TILE_B);
            }
            uint32_t bhi[2][4], blo[2][4];
#pragma unroll
            for (int p = 0; p < 2; p++) {
                uint32_t ko = ((uint32_t)(ks * 32) + kb) ^ b_sw[p];
                uint32_t bd = stb + 2 * TILE_B + b_off[p] + ko;
                ldsm4(bhi[p], bd);
                ldsm4(blo[p], bd + TILE_B);
            }
#pragma unroll
            for (int mt = 0; mt < 4; mt++)
#pragma unroll
                for (int nt = 0; nt < 4; nt++) {
                    const uint32_t* bh = &bhi[nt >> 1][2 * (nt & 1)];
                    const uint32_t* bl = &blo[nt >> 1][2 * (nt & 1)];
                    mma_bf16(acc[mt][nt], ahi[mt], bh);
                    mma_bf16(acc[mt][nt], ahi[mt], bl);
                    mma_bf16(acc[mt][nt], alo[mt], bh);
                }
        }
    }

#pragma unroll
    for (int mt = 0; mt < 4; mt++) {
#pragma unroll
        for (int nt = 0; nt < 4; nt++) {
            int row = m0 + wm * 64 + mt * 16 + (lane >> 2);
            int col = n0 + wn * 32 + nt * 8 + 2 * (lane & 3);
            float2 bv = *(const float2*)&bias[col];
            float2 v0, v1;
            v0.x = acc[mt][nt][0] + bv.x; v0.y = acc[mt][nt][1] + bv.y;
            v1.x = acc[mt][nt][2] + bv.x; v1.y = acc[mt][nt][3] + bv.y;
            *(float2*)&C[(size_t)row * HID + col]       = v0;
            *(float2*)&C[(size_t)(row + 8) * HID + col] = v1;
        }
    }
}

#define STAGE1_B (2 * TILE_B)
#define GEMM1_SMEM (3 * STAGE1_B)

__global__ __launch_bounds__(256, 2)
void gemm1h(const __half* __restrict__ A, const __half* __restrict__ B,
            const float* __restrict__ bias, float* __restrict__ C)
{
    extern __shared__ char smem[];
    const uint32_t sb = smem_to_u32(smem);
    const int tid = threadIdx.x;
    const int wid = tid >> 5;
    const int lane = tid & 31;
    const int m0 = blockIdx.y << 7;
    const int n0 = blockIdx.x << 7;
    const int wm = wid >> 2;
    const int wn = wid & 3;

    const int lrow = tid >> 1;
    const int lcb  = (tid & 1) * 4;
    const uint32_t lrsw = (uint32_t)(lrow & 7) << 4;
    const __half* gsrc[2];
    gsrc[0] = A + (size_t)(m0 + lrow) * HID + lcb * 8;
    gsrc[1] = B + (size_t)(n0 + lrow) * HID + lcb * 8;
    uint32_t ldst[2][4];
#pragma unroll
    for (int t = 0; t < 2; t++)
#pragma unroll
        for (int j = 0; j < 4; j++)
            ldst[t][j] = t * TILE_B + lrow * 128 + ((uint32_t)((lcb + j) * 16) ^ lrsw);

    uint32_t a_off[4], a_sw[4];
#pragma unroll
    for (int mt = 0; mt < 4; mt++) {
        int m = wm * 64 + mt * 16 + (lane & 15);
        a_off[mt] = (uint32_t)m * 128;
        a_sw[mt]  = (uint32_t)(m & 7) << 4;
    }
    const uint32_t ka = (uint32_t)((lane >> 4) << 4);
    uint32_t b_off[2], b_sw[2];
#pragma unroll
    for (int p = 0; p < 2; p++) {
        int n = wn * 32 + p * 16 + (lane & 7) + ((lane & 16) >> 1);
        b_off[p] = (uint32_t)n * 128;
        b_sw[p]  = (uint32_t)(n & 7) << 4;
    }
    const uint32_t kb = (uint32_t)((lane & 8) << 1);

    float acc[4][4][4];
#pragma unroll
    for (int i = 0; i < 4; i++)
#pragma unroll
        for (int j = 0; j < 4; j++)
#pragma unroll
            for (int k = 0; k < 4; k++) acc[i][j][k] = 0.f;

#pragma unroll
    for (int s = 0; s < 2; s++) {
        uint32_t base = sb + s * STAGE1_B;
#pragma unroll
        for (int t = 0; t < 2; t++) {
            const __half* src = gsrc[t] + s * 64;
#pragma unroll
            for (int j = 0; j < 4; j++)
                cp16(base + ldst[t][j], src + j * 8);
        }
        CP_COMMIT();
    }

    for (int c = 0; c < 64; c++) {
        CP_WAIT1();
        __syncthreads();
        const int ldc = c + 2;
        if (ldc < 64) {
            uint32_t base = sb + (ldc % 3) * STAGE1_B;
#pragma unroll
            for (int t = 0; t < 2; t++) {
                const __half* src = gsrc[t] + ldc * 64;
#pragma unroll
                for (int j = 0; j < 4; j++)
                    cp16(base + ldst[t][j], src + j * 8);
            }
        }
        CP_COMMIT();

        const uint32_t stb = sb + (c % 3) * STAGE1_B;
#pragma unroll
        for (int ks = 0; ks < 4; ks++) {
            uint32_t af[4][4];
#pragma unroll
            for (int mt = 0; mt < 4; mt++) {
                uint32_t ko = ((uint32_t)(ks * 32) + ka) ^ a_sw[mt];
                ldsm4(af[mt], stb + a_off[mt] + ko);
            }
            uint32_t bf[2][4];
#pragma unroll
            for (int p = 0; p < 2; p++) {
                uint32_t ko = ((uint32_t)(ks * 32) + kb) ^ b_sw[p];
                ldsm4(bf[p], stb + TILE_B + b_off[p] + ko);
            }
#pragma unroll
            for (int mt = 0; mt < 4; mt++)
#pragma unroll
                for (int nt = 0; nt < 4; nt++)
                    mma_fp16(acc[mt][nt], af[mt], &bf[nt >> 1][2 * (nt & 1)]);
        }
    }

#pragma unroll
    for (int mt = 0; mt < 4; mt++) {
#pragma unroll
        for (int nt = 0; nt < 4; nt++) {
            int row = m0 + wm * 64 + mt * 16 + (lane >> 2);
            int col = n0 + wn * 32 + nt * 8 + 2 * (lane & 3);
            float2 bv = *(const float2*)&bias[col];
            float2 v0, v1;
            v0.x = acc[mt][nt][0] + bv.x; v0.y = acc[mt][nt][1] + bv.y;
            v1.x = acc[mt][nt][2] + bv.x; v1.y = acc[mt][nt][3] + bv.y;
            *(float2*)&C[(size_t)row * HID + col]       = v0;
            *(float2*)&C[(size_t)(row + 8) * HID + col] = v1;
        }
    }
}

// ============================================================================
// RoPE (unchanged)
// ============================================================================
__global__ void rope_kernel(const int* __restrict__ pos) {
    int idx = blockIdx.x * blockDim.x + threadIdx.x;
    if (idx >= TT * NH * 64) return;
    int i = idx & 63;
    int h = (idx >> 6) & 31;
    int t = idx >> 11;
    float p = (float)pos[t];
    float ang = p * g_freq[i];
    double ad = (double)ang;
    float c = (float)cos(ad);
    float s = (float)sin(ad);
    size_t base = ((size_t)t * NH + h) * HD;
    float x1 = g_q[base + i], x2 = g_q[base + 64 + i];
    g_q[base + i]      = x1 * c - x2 * s;
    g_q[base + 64 + i] = x2 * c + x1 * s;
    float y1 = g_k[base + i], y2 = g_k[base + 64 + i];
    g_k[base + i]      = y1 * c - y2 * s;
    g_k[base + 64 + i] = y2 * c + y1 * s;
}

// ============================================================================
// Tensor-core flash attention.
// QK^T: fp16 hi/lo 3-term (softmax-amplified path).
// P.V : fp16 1-term (unamplified; P in [0,1], V fp16).
// CTA = (64 q-rows, head, batch), 4 warps x 16 rows.
// ============================================================================
#define KPAD 136
#define VPAD 74
#define SM_KH 0
#define SM_KL (64 * KPAD)
#define SM_VH (2 * 64 * KPAD)
#define ATTN_SMEM_HALVES (2 * 64 * KPAD + 128 * VPAD)
#define ATTN_SMEM_BYTES  (ATTN_SMEM_HALVES * 2)   // 53760

__global__ __launch_bounds__(128) void attn_kernel(
    const float* __restrict__ past_k, const float* __restrict__ past_v,
    const int* __restrict__ q_start, const int* __restrict__ q_lens,
    const int* __restrict__ kv_lens, const int* __restrict__ boff)
{
    extern __shared__ __half sh[];
    __half* sKh = sh + SM_KH;
    __half* sKl = sh + SM_KL;
    __half* sVh = sh + SM_VH;

    const int b = blockIdx.z, h = blockIdx.y, qt = blockIdx.x;
    const int qlen = q_lens[b];
    if (qt * 64 >= qlen) return;
    const int qs0 = q_start[b];
    const int kvlen = kv_lens[b];
    const int hist = kvlen - qlen;
    const int tid = threadIdx.x;
    const int wrp = tid >> 5;
    const int lane = tid & 31;
    const float scale = 0.08838834764831845f;

    const int lq = lane >> 2;          // 0..7
    const int lc = (lane & 3) * 2;

    // ---- Q fragments, scale folded, hi/lo ----
    const int ra_g = qt * 64 + wrp * 16 + lq;
    const int rb_g = ra_g + 8;
    const float* qrowa = g_q + ((size_t)(qs0 + min(ra_g, qlen - 1)) * NH + h) * HD;
    const float* qrowb = g_q + ((size_t)(qs0 + min(rb_g, qlen - 1)) * NH + h) * HD;
    const bool va_ok = ra_g < qlen, vb_ok = rb_g < qlen;

    uint32_t qhf[8][4], qlf[8][4];
#pragma unroll
    for (int ks = 0; ks < 8; ks++) {
        int k0 = ks * 16 + lc;
        float2 a0 = va_ok ? *(const float2*)&qrowa[k0]     : make_float2(0.f, 0.f);
        float2 a2 = va_ok ? *(const float2*)&qrowa[k0 + 8] : make_float2(0.f, 0.f);
        float2 a1 = vb_ok ? *(const float2*)&qrowb[k0]     : make_float2(0.f, 0.f);
        float2 a3 = vb_ok ? *(const float2*)&qrowb[k0 + 8] : make_float2(0.f, 0.f);
        packsplit(a0.x * scale, a0.y * scale, qhf[ks][0], qlf[ks][0]);
        packsplit(a1.x * scale, a1.y * scale, qhf[ks][1], qlf[ks][1]);
        packsplit(a2.x * scale, a2.y * scale, qhf[ks][2], qlf[ks][2]);
        packsplit(a3.x * scale, a3.y * scale, qhf[ks][3], qlf[ks][3]);
    }

    float o[16][4];
#pragma unroll
    for (int i = 0; i < 16; i++)
#pragma unroll
        for (int j = 0; j < 4; j++) o[i][j] = 0.f;
    float ma = -1e30f, mb = -1e30f, la = 0.f, lb = 0.f;

    const int qhi  = min(qt * 64 + 63, qlen - 1);
    const int nblk = min((kvlen + 63) >> 6, ((hist + qhi) >> 6) + 1);

    const int kr0 = tid >> 5;
    const int kc4 = (tid & 31) * 4;

    for (int kb = 0; kb < nblk; kb++) {
        // ---- fill K (hi/lo) ----
#pragma unroll
        for (int rr = 0; rr < 16; rr++) {
            int r = kr0 + rr * 4;
            int p = kb * 64 + r;
            int pc = min(p, kvlen - 1);
            const float* src;
            if (pc < hist) {
                int blk = boff[b * MAXB + (pc >> 6)];
                src = past_k + ((size_t)(blk * 64 + (pc & 63)) * NH + h) * HD;
            } else {
                src = g_k + ((size_t)(qs0 + pc - hist) * NH + h) * HD;
            }
            float4 v = *(const float4*)&src[kc4];
            float vv[4] = {v.x, v.y, v.z, v.w};
#pragma unroll
            for (int j = 0; j < 4; j++) {
                __half hh = __float2half(vv[j]);
                sKh[r * KPAD + kc4 + j] = hh;
                sKl[r * KPAD + kc4 + j] = __float2half(vv[j] - __half2float(hh));
            }
        }
        // ---- fill V transposed (hi only): thread = dim, iterate keys ----
        for (int kk = 0; kk < 64; kk++) {
            int p = kb * 64 + kk;
            int pc = min(p, kvlen - 1);
            const float* src;
            if (pc < hist) {
                int blk = boff[b * MAXB + (pc >> 6)];
                src = past_v + ((size_t)(blk * 64 + (pc & 63)) * NH + h) * HD;
            } else {
                src = g_v + ((size_t)(qs0 + pc - hist) * NH + h) * HD;
            }
            sVh[tid * VPAD + kk] = __float2half(src[tid]);
        }
        __syncthreads();

        // ---- S = Q K^T (3-term fp16) ----
        float s[8][4];
#pragma unroll
        for (int nt = 0; nt < 8; nt++)
#pragma unroll
            for (int j = 0; j < 4; j++) s[nt][j] = 0.f;
#pragma unroll
        for (int ks = 0; ks < 8; ks++) {
#pragma unroll
            for (int nt = 0; nt < 8; nt++) {
                const __half* kh = &sKh[(nt * 8 + lq) * KPAD + ks * 16 + lc];
                const __half* kl = &sKl[(nt * 8 + lq) * KPAD + ks * 16 + lc];
                uint32_t bh[2] = {*(const uint32_t*)kh, *(const uint32_t*)(kh + 8)};
                uint32_t bl[2] = {*(const uint32_t*)kl, *(const uint32_t*)(kl + 8)};
                mma_fp16(s[nt], qhf[ks], bh);
                mma_fp16(s[nt], qhf[ks], bl);
                mma_fp16(s[nt], qlf[ks], bh);
            }
        }

        // ---- mask + online softmax (fp32) ----
        float mxa = -1e30f, mxb = -1e30f;
#pragma unroll
        for (int nt = 0; nt < 8; nt++) {
            int kg = kb * 64 + nt * 8 + lc;
            s[nt][0] = (kg     <= hist + ra_g) ? s[nt][0] : -1e30f;
            s[nt][1] = (kg + 1 <= hist + ra_g) ? s[nt][1] : -1e30f;
            s[nt][2] = (kg     <= hist + rb_g) ? s[nt][2] : -1e30f;
            s[nt][3] = (kg + 1 <= hist + rb_g) ? s[nt][3] : -1e30f;
            mxa = fmaxf(mxa, fmaxf(s[nt][0], s[nt][1]));
            mxb = fmaxf(mxb, fmaxf(s[nt][2], s[nt][3]));
        }
        mxa = fmaxf(mxa, __shfl_xor_sync(0xffffffffu, mxa, 1));
        mxa = fmaxf(mxa, __shfl_xor_sync(0xffffffffu, mxa, 2));
        mxb = fmaxf(mxb, __shfl_xor_sync(0xffffffffu, mxb, 1));
        mxb = fmaxf(mxb, __shfl_xor_sync(0xffffffffu, mxb, 2));

        float mna = fmaxf(ma, mxa), mnb = fmaxf(mb, mxb);
        float alpha_a = __expf(ma - mna), alpha_b = __expf(mb - mnb);
        ma = mna; mb = mnb;

        float suma = 0.f, sumb = 0.f;
#pragma unroll
        for (int nt = 0; nt < 8; nt++) {
            s[nt][0] = __expf(s[nt][0] - ma);
            s[nt][1] = __expf(s[nt][1] - ma);
            s[nt][2] = __expf(s[nt][2] - mb);
            s[nt][3] = __expf(s[nt][3] - mb);
            suma += s[nt][0] + s[nt][1];
            sumb += s[nt][2] + s[nt][3];
        }
        suma += __shfl_xor_sync(0xffffffffu, suma, 1);
        suma += __shfl_xor_sync(0xffffffffu, suma, 2);
        sumb += __shfl_xor_sync(0xffffffffu, sumb, 1);
        sumb += __shfl_xor_sync(0xffffffffu, sumb, 2);
        la = la * alpha_a + suma;
        lb = lb * alpha_b + sumb;

#pragma unroll
        for (int dt = 0; dt < 16; dt++) {
            o[dt][0] *= alpha_a; o[dt][1] *= alpha_a;
            o[dt][2] *= alpha_b; o[dt][3] *= alpha_b;
        }

        // ---- O += P V (1-term fp16) ----
#pragma unroll
        for (int t = 0; t < 4; t++) {
            uint32_t ph[4];
            ph[0] = packh2(s[2 * t][0],     s[2 * t][1]);
            ph[1] = packh2(s[2 * t][2],     s[2 * t][3]);
            ph[2] = packh2(s[2 * t + 1][0], s[2 * t + 1][1]);
            ph[3] = packh2(s[2 * t + 1][2], s[2 * t + 1][3]);
#pragma unroll
            for (int dt = 0; dt < 16; dt++) {
                const __half* vh = &sVh[(dt * 8 + lq) * VPAD + t * 16 + lc];
                uint32_t bh[2] = {*(const uint32_t*)vh, *(const uint32_t*)(vh + 8)};
                mma_fp16(o[dt], ph, bh);
            }
        }
        __syncthreads();
    }

    // ---- epilogue: normalize, write fp16 to g_xh ----
    float inva = 1.f / la, invb = 1.f / lb;
    __half* outa = g_xh + ((size_t)(qs0 + ra_g) * NH + h) * HD;
    __half* outb = g_xh + ((size_t)(qs0 + rb_g) * NH + h) * HD;
#pragma unroll
    for (int dt = 0; dt < 16; dt++) {
        int d0 = dt * 8 + lc;
        if (va_ok) {
            __half2 w = __halves2half2(__float2half(o[dt][0] * inva),
                                       __float2half(o[dt][1] * inva));
            *(__half2*)&outa[d0] = w;
        }
        if (vb_ok) {
            __half2 w = __halves2half2(__float2half(o[dt][2] * invb),
                                       __float2half(o[dt][3] * invb));
            *(__half2*)&outb[d0] = w;
        }
    }
}

// ============================================================================
extern "C" void kernel_launch(void* const* d_in, const int* in_sizes, int n_in,
                              void* d_out, int out_size) {
    const float* x      = (const float*)d_in[0];
    const int*   pos    = (const int*)d_in[1];
    const int*   qstart = (const int*)d_in[2];
    const int*   qlens  = (const int*)d_in[3];
    const int*   kvlens = (const int*)d_in[4];
    const int*   boff   = (const int*)d_in[5];
    const float* pk     = (const float*)d_in[6];
    const float* pv     = (const float*)d_in[7];
    const float* Wq = (const float*)d_in[8];
    const float* bq = (const float*)d_in[9];
    const float* Wk = (const float*)d_in[10];
    const float* bk = (const float*)d_in[11];
    const float* Wv = (const float*)d_in[12];
    const float* bv = (const float*)d_in[13];
    const float* Wo = (const float*)d_in[14];
    const float* bo = (const float*)d_in[15];
    float* out = (float*)d_out;

    float* vp;
    cudaGetSymbolAddress((void**)&vp, g_v);
    __nv_bfloat16 *xhi, *xlo;
    __half *xh, *w3h, *w4h;
    cudaGetSymbolAddress((void**)&xhi, g_xhi);
    cudaGetSymbolAddress((void**)&xlo, g_xlo);
    cudaGetSymbolAddress((void**)&xh,  g_xh);
    cudaGetSymbolAddress((void**)&w3h, g_w3h);
    cudaGetSymbolAddress((void**)&w4h, g_w4h);

    cudaFuncSetAttribute(gemm3qk, cudaFuncAttributeMaxDynamicSharedMemorySize, GEMM3_SMEM);
    cudaFuncSetAttribute(gemm1h,  cudaFuncAttributeMaxDynamicSharedMemorySize, GEMM1_SMEM);
    cudaFuncSetAttribute(attn_kernel, cudaFuncAttributeMaxDynamicSharedMemorySize, ATTN_SMEM_BYTES);

    const int n4x = TT * HID / 4;
    const int n4w = HID * HID / 4;
    dim3 ggqk(HID / 128, TT / 128, 2);
    dim3 gg(HID / 128, TT / 128);

    wsplit_kernel<<<dim3((n4w + 255) / 256, 1, 4), 256>>>(Wq, Wk, Wv, Wo);
    xsplit3_kernel<<<(n4x + 255) / 256, 256>>>(x, n4x);
    gemm3qk<<<ggqk, 256, GEMM3_SMEM>>>(xhi, xlo, bq, bk);
    gemm1h<<<gg, 256, GEMM1_SMEM>>>(xh, w3h, bv, vp);
    init_freq_kernel<<<1, 64>>>();
    rope_kernel<<<(TT * NH * 64 + 255) / 256, 256>>>(pos);
    attn_kernel<<<dim3(16, NH, NBAT), 128, ATTN_SMEM_BYTES>>>(pk, pv, qstart, qlens,
                                                              kvlens, boff);
    gemm1h<<<gg, 256, GEMM1_SMEM>>>(xh, w4h, bo, out);
}

// round 16
// speedup vs baseline: 1.2899x; 1.1597x over previous
#include <cuda_runtime.h>
#include <cuda_bf16.h>
#include <cuda_fp16.h>
#include <cstdint>

#define TT   3072
#define HID  4096
#define NH   32
#define HD   128
#define NBAT 4
#define MAXB 24
#define MAXKV 1536

// ============================================================================
// helpers (baseline PTX only — no sm_103a-gated features)
// ============================================================================
__device__ __forceinline__ uint32_t smem_to_u32(const void* p) {
    uint32_t a;
    asm("{ .reg .u64 t; cvta.to.shared.u64 t, %1; cvt.u32.u64 %0, t; }" : "=r"(a) : "l"(p));
    return a;
}
__device__ __forceinline__ void cp16(uint32_t dst, const void* src) {
    asm volatile("cp.async.cg.shared.global [%0], [%1], 16;" :: "r"(dst), "l"(src));
}
#define CP_COMMIT() asm volatile("cp.async.commit_group;" ::: "memory")
#define CP_WAIT1()  asm volatile("cp.async.wait_group 1;" ::: "memory")
#define CP_WAIT0()  asm volatile("cp.async.wait_group 0;" ::: "memory")

__device__ __forceinline__ void ldsm4(uint32_t* r, uint32_t addr) {
    asm volatile("ldmatrix.sync.aligned.m8n8.x4.shared.b16 {%0,%1,%2,%3}, [%4];"
        : "=r"(r[0]), "=r"(r[1]), "=r"(r[2]), "=r"(r[3]) : "r"(addr));
}
__device__ __forceinline__ void ldsm4t(uint32_t* r, uint32_t addr) {
    asm volatile("ldmatrix.sync.aligned.m8n8.x4.trans.shared.b16 {%0,%1,%2,%3}, [%4];"
        : "=r"(r[0]), "=r"(r[1]), "=r"(r[2]), "=r"(r[3]) : "r"(addr));
}
__device__ __forceinline__ void mma_bf16(float* c, const uint32_t* a, const uint32_t* b) {
    asm volatile("mma.sync.aligned.m16n8k16.row.col.f32.bf16.bf16.f32 "
        "{%0,%1,%2,%3}, {%4,%5,%6,%7}, {%8,%9}, {%0,%1,%2,%3};"
        : "+f"(c[0]), "+f"(c[1]), "+f"(c[2]), "+f"(c[3])
        : "r"(a[0]), "r"(a[1]), "r"(a[2]), "r"(a[3]), "r"(b[0]), "r"(b[1]));
}
__device__ __forceinline__ void mma_fp16(float* c, const uint32_t* a, const uint32_t* b) {
    asm volatile("mma.sync.aligned.m16n8k16.row.col.f32.f16.f16.f32 "
        "{%0,%1,%2,%3}, {%4,%5,%6,%7}, {%8,%9}, {%0,%1,%2,%3};"
        : "+f"(c[0]), "+f"(c[1]), "+f"(c[2]), "+f"(c[3])
        : "r"(a[0]), "r"(a[1]), "r"(a[2]), "r"(a[3]), "r"(b[0]), "r"(b[1]));
}
__device__ __forceinline__ void packsplit(float a, float b, uint32_t& hi, uint32_t& lo) {
    __half ha = __float2half(a), hb = __float2half(b);
    __half la = __float2half(a - __half2float(ha));
    __half lb = __float2half(b - __half2float(hb));
    __half2 H = __halves2half2(ha, hb), L = __halves2half2(la, lb);
    hi = *(uint32_t*)&H; lo = *(uint32_t*)&L;
}
__device__ __forceinline__ uint32_t packh2(float a, float b) {
    __half2 H = __halves2half2(__float2half(a), __float2half(b));
    return *(uint32_t*)&H;
}

// ---- workspace (static device arrays; no allocation) ----
__device__ float g_q[(size_t)TT * HID];
__device__ float g_k[(size_t)TT * HID];
__device__ float g_v[(size_t)TT * HID];
__device__ float g_freq[64];
__device__ __nv_bfloat16 g_xhi[(size_t)TT * HID];
__device__ __nv_bfloat16 g_xlo[(size_t)TT * HID];
__device__ __half        g_xh [(size_t)TT * HID];
__device__ __nv_bfloat16 g_w1hi[(size_t)HID * HID];
__device__ __nv_bfloat16 g_w1lo[(size_t)HID * HID];
__device__ __nv_bfloat16 g_w2hi[(size_t)HID * HID];
__device__ __nv_bfloat16 g_w2lo[(size_t)HID * HID];
__device__ __half        g_w3h [(size_t)HID * HID];
__device__ __half        g_w4h [(size_t)HID * HID];
// linearized, fp16-converted KV for attention: [b][pos][h*128+d]
__device__ __half g_kh[(size_t)NBAT * MAXKV * HID];
__device__ __half g_kl[(size_t)NBAT * MAXKV * HID];
__device__ __half g_vv[(size_t)NBAT * MAXKV * HID];

__global__ void init_freq_kernel() {
    int i = threadIdx.x;
    if (i < 64) g_freq[i] = (float)exp(-(double)i * (log(10000.0) / 64.0));
}

// ============================================================================
// splits
// ============================================================================
__device__ __forceinline__ void split_bf16(const float* __restrict__ x,
                                           __nv_bfloat16* __restrict__ hi,
                                           __nv_bfloat16* __restrict__ lo, int i)
{
    float4 v = ((const float4*)x)[i];
    float vv[4] = {v.x, v.y, v.z, v.w};
    __nv_bfloat16 h[4], l[4];
#pragma unroll
    for (int j = 0; j < 4; j++) {
        h[j] = __float2bfloat16(vv[j]);
        l[j] = __float2bfloat16(vv[j] - __bfloat162float(h[j]));
    }
    ((__nv_bfloat162*)hi)[2 * i + 0] = __nv_bfloat162(h[0], h[1]);
    ((__nv_bfloat162*)hi)[2 * i + 1] = __nv_bfloat162(h[2], h[3]);
    ((__nv_bfloat162*)lo)[2 * i + 0] = __nv_bfloat162(l[0], l[1]);
    ((__nv_bfloat162*)lo)[2 * i + 1] = __nv_bfloat162(l[2], l[3]);
}
__device__ __forceinline__ void conv_fp16(const float* __restrict__ x,
                                          __half* __restrict__ out, int i)
{
    float4 v = ((const float4*)x)[i];
    ((__half2*)out)[2 * i + 0] = __half2(__float2half(v.x), __float2half(v.y));
    ((__half2*)out)[2 * i + 1] = __half2(__float2half(v.z), __float2half(v.w));
}

__global__ __launch_bounds__(256) void xsplit3_kernel(const float* __restrict__ x, int n4)
{
    int i = blockIdx.x * blockDim.x + threadIdx.x;
    if (i >= n4) return;
    float4 v = ((const float4*)x)[i];
    float vv[4] = {v.x, v.y, v.z, v.w};
    __nv_bfloat16 h[4], l[4];
    __half f[4];
#pragma unroll
    for (int j = 0; j < 4; j++) {
        h[j] = __float2bfloat16(vv[j]);
        l[j] = __float2bfloat16(vv[j] - __bfloat162float(h[j]));
        f[j] = __float2half(vv[j]);
    }
    ((__nv_bfloat162*)g_xhi)[2 * i + 0] = __nv_bfloat162(h[0], h[1]);
    ((__nv_bfloat162*)g_xhi)[2 * i + 1] = __nv_bfloat162(h[2], h[3]);
    ((__nv_bfloat162*)g_xlo)[2 * i + 0] = __nv_bfloat162(l[0], l[1]);
    ((__nv_bfloat162*)g_xlo)[2 * i + 1] = __nv_bfloat162(l[2], l[3]);
    ((__half2*)g_xh)[2 * i + 0] = __half2(f[0], f[1]);
    ((__half2*)g_xh)[2 * i + 1] = __half2(f[2], f[3]);
}

__global__ __launch_bounds__(256) void wsplit_kernel(
    const float* __restrict__ Wq, const float* __restrict__ Wk,
    const float* __restrict__ Wv, const float* __restrict__ Wo)
{
    int i = blockIdx.x * blockDim.x + threadIdx.x;
    const int n4 = HID * HID / 4;
    if (i >= n4) return;
    int z = blockIdx.z;
    if (z == 0)      split_bf16(Wq, g_w1hi, g_w1lo, i);
    else if (z == 1) split_bf16(Wk, g_w2hi, g_w2lo, i);
    else if (z == 2) conv_fp16(Wv, g_w3h, i);
    else             conv_fp16(Wo, g_w4h, i);
}

// ============================================================================
// kvprep: gather paged cache + fresh K/V into linear fp16 buffers.
// One CTA (128 threads) per (b, pos). K -> hi/lo planes, V -> hi plane.
// Run AFTER rope (fresh K rotated) and AFTER the V GEMM.
// ============================================================================
__global__ __launch_bounds__(128) void kvprep_kernel(
    const float* __restrict__ past_k, const float* __restrict__ past_v,
    const int* __restrict__ q_start, const int* __restrict__ q_lens,
    const int* __restrict__ kv_lens, const int* __restrict__ boff)
{
    const int b = blockIdx.x / MAXKV;
    const int pos = blockIdx.x % MAXKV;
    const int kvlen = kv_lens[b];
    if (pos >= kvlen) return;
    const int hist = kvlen - q_lens[b];
    const int tid = threadIdx.x;

    const float *ksrc, *vsrc;
    if (pos < hist) {
        int blk = boff[b * MAXB + (pos >> 6)];
        size_t base = (size_t)(blk * 64 + (pos & 63)) * HID;
        ksrc = past_k + base;
        vsrc = past_v + base;
    } else {
        size_t base = (size_t)(q_start[b] + pos - hist) * HID;
        ksrc = g_k + base;
        vsrc = g_v + base;
    }
    size_t dst = (size_t)(b * MAXKV + pos) * HID;
#pragma unroll
    for (int i = 0; i < 8; i++) {
        int idx = tid + i * 128;     // float4 index within 4096 floats
        float4 kv4 = ((const float4*)ksrc)[idx];
        float kk[4] = {kv4.x, kv4.y, kv4.z, kv4.w};
        __half h[4], l[4];
#pragma unroll
        for (int j = 0; j < 4; j++) {
            h[j] = __float2half(kk[j]);
            l[j] = __float2half(kk[j] - __half2float(h[j]));
        }
        ((__half2*)(g_kh + dst))[2 * idx + 0] = __half2(h[0], h[1]);
        ((__half2*)(g_kh + dst))[2 * idx + 1] = __half2(h[2], h[3]);
        ((__half2*)(g_kl + dst))[2 * idx + 0] = __half2(l[0], l[1]);
        ((__half2*)(g_kl + dst))[2 * idx + 1] = __half2(l[2], l[3]);
        float4 vv4 = ((const float4*)vsrc)[idx];
        ((__half2*)(g_vv + dst))[2 * idx + 0] =
            __half2(__float2half(vv4.x), __float2half(vv4.y));
        ((__half2*)(g_vv + dst))[2 * idx + 1] =
            __half2(__float2half(vv4.z), __float2half(vv4.w));
    }
}

// ============================================================================
// GEMMs (validated, unchanged)
// ============================================================================
#define TILE_B  16384
#define STAGE3_B (4 * TILE_B)
#define GEMM3_SMEM (3 * STAGE3_B)

__global__ __launch_bounds__(256)
void gemm3qk(const __nv_bfloat16* __restrict__ Ahi, const __nv_bfloat16* __restrict__ Alo,
             const float* __restrict__ bq, const float* __restrict__ bk)
{
    const int zz = blockIdx.z;
    const __nv_bfloat16* __restrict__ Bhi = zz ? g_w2hi : g_w1hi;
    const __nv_bfloat16* __restrict__ Blo = zz ? g_w2lo : g_w1lo;
    const float* __restrict__ bias = zz ? bk : bq;
    float* __restrict__ C = zz ? g_k : g_q;

    extern __shared__ char smem[];
    const uint32_t sb = smem_to_u32(smem);
    const int tid = threadIdx.x;
    const int wid = tid >> 5;
    const int lane = tid & 31;
    const int m0 = blockIdx.y << 7;
    const int n0 = blockIdx.x << 7;
    const int wm = wid >> 2;
    const int wn = wid & 3;

    const int lrow = tid >> 1;
    const int lcb  = (tid & 1) * 4;
    const uint32_t lrsw = (uint32_t)(lrow & 7) << 4;
    const __nv_bfloat16* gsrc[4];
    gsrc[0] = Ahi + (size_t)(m0 + lrow) * HID + lcb * 8;
    gsrc[1] = Alo + (size_t)(m0 + lrow) * HID + lcb * 8;
    gsrc[2] = Bhi + (size_t)(n0 + lrow) * HID + lcb * 8;
    gsrc[3] = Blo + (size_t)(n0 + lrow) * HID + lcb * 8;
    uint32_t ldst[4][4];
#pragma unroll
    for (int t = 0; t < 4; t++)
#pragma unroll
        for (int j = 0; j < 4; j++)
            ldst[t][j] = t * TILE_B + lrow * 128 + ((uint32_t)((lcb + j) * 16) ^ lrsw);

    uint32_t a_off[4], a_sw[4];
#pragma unroll
    for (int mt = 0; mt < 4; mt++) {
        int m = wm * 64 + mt * 16 + (lane & 15);
        a_off[mt] = (uint32_t)m * 128;
        a_sw[mt]  = (uint32_t)(m & 7) << 4;
    }
    const uint32_t ka = (uint32_t)((lane >> 4) << 4);
    uint32_t b_off[2], b_sw[2];
#pragma unroll
    for (int p = 0; p < 2; p++) {
        int n = wn * 32 + p * 16 + (lane & 7) + ((lane & 16) >> 1);
        b_off[p] = (uint32_t)n * 128;
        b_sw[p]  = (uint32_t)(n & 7) << 4;
    }
    const uint32_t kb = (uint32_t)((lane & 8) << 1);

    float acc[4][4][4];
#pragma unroll
    for (int i = 0; i < 4; i++)
#pragma unroll
        for (int j = 0; j < 4; j++)
#pragma unroll
            for (int k = 0; k < 4; k++) acc[i][j][k] = 0.f;

#pragma unroll
    for (int s = 0; s < 2; s++) {
        uint32_t base = sb + s * STAGE3_B;
#pragma unroll
        for (int t = 0; t < 4; t++) {
            const __nv_bfloat16* src = gsrc[t] + s * 64;
#pragma unroll
            for (int j = 0; j < 4; j++)
                cp16(base + ldst[t][j], src + j * 8);
        }
        CP_COMMIT();
    }

    for (int c = 0; c < 64; c++) {
        CP_WAIT1();
        __syncthreads();
        const int ldc = c + 2;
        if (ldc < 64) {
            uint32_t base = sb + (ldc % 3) * STAGE3_B;
#pragma unroll
            for (int t = 0; t < 4; t++) {
                const __nv_bfloat16* src = gsrc[t] + ldc * 64;
#pragma unroll
                for (int j = 0; j < 4; j++)
                    cp16(base + ldst[t][j], src + j * 8);
            }
        }
        CP_COMMIT();

        const uint32_t stb = sb + (c % 3) * STAGE3_B;
#pragma unroll
        for (int ks = 0; ks < 4; ks++) {
            uint32_t ahi[4][4], alo[4][4];
#pragma unroll
            for (int mt = 0; mt < 4; mt++) {
                uint32_t ko = ((uint32_t)(ks * 32) + ka) ^ a_sw[mt];
                uint32_t ad = stb + a_off[mt] + ko;
                ldsm4(ahi[mt], ad);
                ldsm4(alo[mt], ad + TILE_B);
            }
            uint32_t bhi[2][4], blo[2][4];
#pragma unroll
            for (int p = 0; p < 2; p++) {
                uint32_t ko = ((uint32_t)(ks * 32) + kb) ^ b_sw[p];
                uint32_t bd = stb + 2 * TILE_B + b_off[p] + ko;
                ldsm4(bhi[p], bd);
                ldsm4(blo[p], bd + TILE_B);
            }
#pragma unroll
            for (int mt = 0; mt < 4; mt++)
#pragma unroll
                for (int nt = 0; nt < 4; nt++) {
                    const uint32_t* bh = &bhi[nt >> 1][2 * (nt & 1)];
                    const uint32_t* bl = &blo[nt >> 1][2 * (nt & 1)];
                    mma_bf16(acc[mt][nt], ahi[mt], bh);
                    mma_bf16(acc[mt][nt], ahi[mt], bl);
                    mma_bf16(acc[mt][nt], alo[mt], bh);
                }
        }
    }

#pragma unroll
    for (int mt = 0; mt < 4; mt++) {
#pragma unroll
        for (int nt = 0; nt < 4; nt++) {
            int row = m0 + wm * 64 + mt * 16 + (lane >> 2);
            int col = n0 + wn * 32 + nt * 8 + 2 * (lane & 3);
            float2 bv = *(const float2*)&bias[col];
            float2 v0, v1;
            v0.x = acc[mt][nt][0] + bv.x; v0.y = acc[mt][nt][1] + bv.y;
            v1.x = acc[mt][nt][2] + bv.x; v1.y = acc[mt][nt][3] + bv.y;
            *(float2*)&C[(size_t)row * HID + col]       = v0;
            *(float2*)&C[(size_t)(row + 8) * HID + col] = v1;
        }
    }
}

#define STAGE1_B (2 * TILE_B)
#define GEMM1_SMEM (3 * STAGE1_B)

__global__ __launch_bounds__(256, 2)
void gemm1h(const __half* __restrict__ A, const __half* __restrict__ B,
            const float* __restrict__ bias, float* __restrict__ C)
{
    extern __shared__ char smem[];
    const uint32_t sb = smem_to_u32(smem);
    const int tid = threadIdx.x;
    const int wid = tid >> 5;
    const int lane = tid & 31;
    const int m0 = blockIdx.y << 7;
    const int n0 = blockIdx.x << 7;
    const int wm = wid >> 2;
    const int wn = wid & 3;

    const int lrow = tid >> 1;
    const int lcb  = (tid & 1) * 4;
    const uint32_t lrsw = (uint32_t)(lrow & 7) << 4;
    const __half* gsrc[2];
    gsrc[0] = A + (size_t)(m0 + lrow) * HID + lcb * 8;
    gsrc[1] = B + (size_t)(n0 + lrow) * HID + lcb * 8;
    uint32_t ldst[2][4];
#pragma unroll
    for (int t = 0; t < 2; t++)
#pragma unroll
        for (int j = 0; j < 4; j++)
            ldst[t][j] = t * TILE_B + lrow * 128 + ((uint32_t)((lcb + j) * 16) ^ lrsw);

    uint32_t a_off[4], a_sw[4];
#pragma unroll
    for (int mt = 0; mt < 4; mt++) {
        int m = wm * 64 + mt * 16 + (lane & 15);
        a_off[mt] = (uint32_t)m * 128;
        a_sw[mt]  = (uint32_t)(m & 7) << 4;
    }
    const uint32_t ka = (uint32_t)((lane >> 4) << 4);
    uint32_t b_off[2], b_sw[2];
#pragma unroll
    for (int p = 0; p < 2; p++) {
        int n = wn * 32 + p * 16 + (lane & 7) + ((lane & 16) >> 1);
        b_off[p] = (uint32_t)n * 128;
        b_sw[p]  = (uint32_t)(n & 7) << 4;
    }
    const uint32_t kb = (uint32_t)((lane & 8) << 1);

    float acc[4][4][4];
#pragma unroll
    for (int i = 0; i < 4; i++)
#pragma unroll
        for (int j = 0; j < 4; j++)
#pragma unroll
            for (int k = 0; k < 4; k++) acc[i][j][k] = 0.f;

#pragma unroll
    for (int s = 0; s < 2; s++) {
        uint32_t base = sb + s * STAGE1_B;
#pragma unroll
        for (int t = 0; t < 2; t++) {
            const __half* src = gsrc[t] + s * 64;
#pragma unroll
            for (int j = 0; j < 4; j++)
                cp16(base + ldst[t][j], src + j * 8);
        }
        CP_COMMIT();
    }

    for (int c = 0; c < 64; c++) {
        CP_WAIT1();
        __syncthreads();
        const int ldc = c + 2;
        if (ldc < 64) {
            uint32_t base = sb + (ldc % 3) * STAGE1_B;
#pragma unroll
            for (int t = 0; t < 2; t++) {
                const __half* src = gsrc[t] + ldc * 64;
#pragma unroll
                for (int j = 0; j < 4; j++)
                    cp16(base + ldst[t][j], src + j * 8);
            }
        }
        CP_COMMIT();

        const uint32_t stb = sb + (c % 3) * STAGE1_B;
#pragma unroll
        for (int ks = 0; ks < 4; ks++) {
            uint32_t af[4][4];
#pragma unroll
            for (int mt = 0; mt < 4; mt++) {
                uint32_t ko = ((uint32_t)(ks * 32) + ka) ^ a_sw[mt];
                ldsm4(af[mt], stb + a_off[mt] + ko);
            }
            uint32_t bf[2][4];
#pragma unroll
            for (int p = 0; p < 2; p++) {
                uint32_t ko = ((uint32_t)(ks * 32) + kb) ^ b_sw[p];
                ldsm4(bf[p], stb + TILE_B + b_off[p] + ko);
            }
#pragma unroll
            for (int mt = 0; mt < 4; mt++)
#pragma unroll
                for (int nt = 0; nt < 4; nt++)
                    mma_fp16(acc[mt][nt], af[mt], &bf[nt >> 1][2 * (nt & 1)]);
        }
    }

#pragma unroll
    for (int mt = 0; mt < 4; mt++) {
#pragma unroll
        for (int nt = 0; nt < 4; nt++) {
            int row = m0 + wm * 64 + mt * 16 + (lane >> 2);
            int col = n0 + wn * 32 + nt * 8 + 2 * (lane & 3);
            float2 bv = *(const float2*)&bias[col];
            float2 v0, v1;
            v0.x = acc[mt][nt][0] + bv.x; v0.y = acc[mt][nt][1] + bv.y;
            v1.x = acc[mt][nt][2] + bv.x; v1.y = acc[mt][nt][3] + bv.y;
            *(float2*)&C[(size_t)row * HID + col]       = v0;
            *(float2*)&C[(size_t)(row + 8) * HID + col] = v1;
        }
    }
}

// ============================================================================
// RoPE (unchanged)
// ============================================================================
__global__ void rope_kernel(const int* __restrict__ pos) {
    int idx = blockIdx.x * blockDim.x + threadIdx.x;
    if (idx >= TT * NH * 64) return;
    int i = idx & 63;
    int h = (idx >> 6) & 31;
    int t = idx >> 11;
    float p = (float)pos[t];
    float ang = p * g_freq[i];
    double ad = (double)ang;
    float c = (float)cos(ad);
    float s = (float)sin(ad);
    size_t base = ((size_t)t * NH + h) * HD;
    float x1 = g_q[base + i], x2 = g_q[base + 64 + i];
    g_q[base + i]      = x1 * c - x2 * s;
    g_q[base + 64 + i] = x2 * c + x1 * s;
    float y1 = g_k[base + i], y2 = g_k[base + 64 + i];
    g_k[base + i]      = y1 * c - y2 * s;
    g_k[base + 64 + i] = y2 * c + y1 * s;
}

// ============================================================================
// Tensor-core flash attention, pre-converted fp16 KV (cp.async fills, ldmatrix).
// QK^T: fp16 hi/lo 3-term; P.V: fp16 1-term. CTA = (64 q, head, batch).
// Smem rows padded to 136 halves (272B) -> conflict-free ldsm phases.
// ============================================================================
#define KROW 136
#define SM_KHB 0
#define SM_KLB (64 * KROW * 2)
#define SM_VB  (2 * 64 * KROW * 2)
#define ATTN_SMEM_BYTES (3 * 64 * KROW * 2)   // 52224

__global__ __launch_bounds__(128) void attn_kernel(
    const int* __restrict__ q_start, const int* __restrict__ q_lens,
    const int* __restrict__ kv_lens)
{
    extern __shared__ __half sh[];
    const uint32_t sbase = smem_to_u32(sh);

    const int b = blockIdx.z, h = blockIdx.y, qt = blockIdx.x;
    const int qlen = q_lens[b];
    if (qt * 64 >= qlen) return;
    const int qs0 = q_start[b];
    const int kvlen = kv_lens[b];
    const int hist = kvlen - qlen;
    const int tid = threadIdx.x;
    const int wrp = tid >> 5;
    const int lane = tid & 31;
    const float scale = 0.08838834764831845f;

    const int lq = lane >> 2;
    const int lc = (lane & 3) * 2;

    // ---- Q fragments, scale folded, hi/lo ----
    const int ra_g = qt * 64 + wrp * 16 + lq;
    const int rb_g = ra_g + 8;
    const float* qrowa = g_q + ((size_t)(qs0 + min(ra_g, qlen - 1)) * NH + h) * HD;
    const float* qrowb = g_q + ((size_t)(qs0 + min(rb_g, qlen - 1)) * NH + h) * HD;
    const bool va_ok = ra_g < qlen, vb_ok = rb_g < qlen;

    uint32_t qhf[8][4], qlf[8][4];
#pragma unroll
    for (int ks = 0; ks < 8; ks++) {
        int k0 = ks * 16 + lc;
        float2 a0 = va_ok ? *(const float2*)&qrowa[k0]     : make_float2(0.f, 0.f);
        float2 a2 = va_ok ? *(const float2*)&qrowa[k0 + 8] : make_float2(0.f, 0.f);
        float2 a1 = vb_ok ? *(const float2*)&qrowb[k0]     : make_float2(0.f, 0.f);
        float2 a3 = vb_ok ? *(const float2*)&qrowb[k0 + 8] : make_float2(0.f, 0.f);
        packsplit(a0.x * scale, a0.y * scale, qhf[ks][0], qlf[ks][0]);
        packsplit(a1.x * scale, a1.y * scale, qhf[ks][1], qlf[ks][1]);
        packsplit(a2.x * scale, a2.y * scale, qhf[ks][2], qlf[ks][2]);
        packsplit(a3.x * scale, a3.y * scale, qhf[ks][3], qlf[ks][3]);
    }

    float o[16][4];
#pragma unroll
    for (int i = 0; i < 16; i++)
#pragma unroll
        for (int j = 0; j < 4; j++) o[i][j] = 0.f;
    float ma = -1e30f, mb = -1e30f, la = 0.f, lb = 0.f;

    const int qhi  = min(qt * 64 + 63, qlen - 1);
    const int nblk = min((kvlen + 63) >> 6, ((hist + qhi) >> 6) + 1);

    // fill mapping: thread -> row (tid>>1), half-row (tid&1), 8 chunks of 16B
    const int frow = tid >> 1;
    const int fhalf = tid & 1;
    const size_t gstride = HID;                      // halves per key row
    const __half* gKh = g_kh + ((size_t)b * MAXKV) * HID + (size_t)h * HD + fhalf * 64;
    const __half* gKl = g_kl + ((size_t)b * MAXKV) * HID + (size_t)h * HD + fhalf * 64;
    const __half* gV  = g_vv + ((size_t)b * MAXKV) * HID + (size_t)h * HD + fhalf * 64;
    const uint32_t sdst = sbase + frow * (KROW * 2) + fhalf * 128;

    // ldsm address components
    // K (S-mma B): non-trans, rows = keys; key = p*16 + (lane&7) + ((lane&16)>>1),
    //              byte col = ks*32 + ((lane&8)<<1)
    const uint32_t k_row = (uint32_t)((lane & 7) + ((lane & 16) >> 1));
    const uint32_t k_cb  = (uint32_t)((lane & 8) << 1);
    // V (PV-mma B): trans, rows = keys; key = t*16 + (lane&15),
    //               byte col = dt2*32 + ((lane>>4)<<4)
    const uint32_t v_row = (uint32_t)(lane & 15);
    const uint32_t v_cb  = (uint32_t)(((lane >> 4) & 1) << 4);

    for (int kb = 0; kb < nblk; kb++) {
        // ---- async fill: K hi, K lo, V (each 64 rows x 256B) ----
        const size_t goff = (size_t)(kb * 64 + frow) * gstride;
#pragma unroll
        for (int j = 0; j < 8; j++) {
            cp16(sdst + SM_KHB + j * 16, gKh + goff + j * 8);
            cp16(sdst + SM_KLB + j * 16, gKl + goff + j * 8);
            cp16(sdst + SM_VB  + j * 16, gV  + goff + j * 8);
        }
        CP_COMMIT();
        CP_WAIT0();
        __syncthreads();

        // ---- S = Q K^T (3-term fp16) ----
        float s[8][4];
#pragma unroll
        for (int nt = 0; nt < 8; nt++)
#pragma unroll
            for (int j = 0; j < 4; j++) s[nt][j] = 0.f;
#pragma unroll
        for (int ks = 0; ks < 8; ks++) {
#pragma unroll
            for (int p = 0; p < 4; p++) {
                uint32_t ad = sbase + (p * 16 + k_row) * (KROW * 2)
                            + (uint32_t)(ks * 32) + k_cb;
                uint32_t bh[4], bl[4];
                ldsm4(bh, ad + SM_KHB);
                ldsm4(bl, ad + SM_KLB);
#pragma unroll
                for (int sub = 0; sub < 2; sub++) {
                    int nt = p * 2 + sub;
                    mma_fp16(s[nt], qhf[ks], &bh[2 * sub]);
                    mma_fp16(s[nt], qhf[ks], &bl[2 * sub]);
                    mma_fp16(s[nt], qlf[ks], &bh[2 * sub]);
                }
            }
        }

        // ---- mask + online softmax (fp32) ----
        float mxa = -1e30f, mxb = -1e30f;
#pragma unroll
        for (int nt = 0; nt < 8; nt++) {
            int kg = kb * 64 + nt * 8 + lc;
            s[nt][0] = (kg     <= hist + ra_g) ? s[nt][0] : -1e30f;
            s[nt][1] = (kg + 1 <= hist + ra_g) ? s[nt][1] : -1e30f;
            s[nt][2] = (kg     <= hist + rb_g) ? s[nt][2] : -1e30f;
            s[nt][3] = (kg + 1 <= hist + rb_g) ? s[nt][3] : -1e30f;
            mxa = fmaxf(mxa, fmaxf(s[nt][0], s[nt][1]));
            mxb = fmaxf(mxb, fmaxf(s[nt][2], s[nt][3]));
        }
        mxa = fmaxf(mxa, __shfl_xor_sync(0xffffffffu, mxa, 1));
        mxa = fmaxf(mxa, __shfl_xor_sync(0xffffffffu, mxa, 2));
        mxb = fmaxf(mxb, __shfl_xor_sync(0xffffffffu, mxb, 1));
        mxb = fmaxf(mxb, __shfl_xor_sync(0xffffffffu, mxb, 2));

        float mna = fmaxf(ma, mxa), mnb = fmaxf(mb, mxb);
        float alpha_a = __expf(ma - mna), alpha_b = __expf(mb - mnb);
        ma = mna; mb = mnb;

        float suma = 0.f, sumb = 0.f;
#pragma unroll
        for (int nt = 0; nt < 8; nt++) {
            s[nt][0] = __expf(s[nt][0] - ma);
            s[nt][1] = __expf(s[nt][1] - ma);
            s[nt][2] = __expf(s[nt][2] - mb);
            s[nt][3] = __expf(s[nt][3] - mb);
            suma += s[nt][0] + s[nt][1];
            sumb += s[nt][2] + s[nt][3];
        }
        suma += __shfl_xor_sync(0xffffffffu, suma, 1);
        suma += __shfl_xor_sync(0xffffffffu, suma, 2);
        sumb += __shfl_xor_sync(0xffffffffu, sumb, 1);
        sumb += __shfl_xor_sync(0xffffffffu, sumb, 2);
        la = la * alpha_a + suma;
        lb = lb * alpha_b + sumb;

#pragma unroll
        for (int dt = 0; dt < 16; dt++) {
            o[dt][0] *= alpha_a; o[dt][1] *= alpha_a;
            o[dt][2] *= alpha_b; o[dt][3] *= alpha_b;
        }

        // ---- O += P V (1-term fp16); V b-frags via ldmatrix.trans ----
#pragma unroll
        for (int t = 0; t < 4; t++) {
            uint32_t ph[4];
            ph[0] = packh2(s[2 * t][0],     s[2 * t][1]);
            ph[1] = packh2(s[2 * t][2],     s[2 * t][3]);
            ph[2] = packh2(s[2 * t + 1][0], s[2 * t + 1][1]);
            ph[3] = packh2(s[2 * t + 1][2], s[2 * t + 1][3]);
            uint32_t vrow = sbase + SM_VB + (t * 16 + v_row) * (KROW * 2) + v_cb;
#pragma unroll
            for (int dt2 = 0; dt2 < 8; dt2++) {
                uint32_t vt[4];
                ldsm4t(vt, vrow + dt2 * 32);
                mma_fp16(o[2 * dt2],     ph, &vt[0]);
                mma_fp16(o[2 * dt2 + 1], ph, &vt[2]);
            }
        }
        __syncthreads();
    }

    // ---- epilogue: normalize, write fp16 to g_xh ----
    float inva = 1.f / la, invb = 1.f / lb;
    __half* outa = g_xh + ((size_t)(qs0 + ra_g) * NH + h) * HD;
    __half* outb = g_xh + ((size_t)(qs0 + rb_g) * NH + h) * HD;
#pragma unroll
    for (int dt = 0; dt < 16; dt++) {
        int d0 = dt * 8 + lc;
        if (va_ok) {
            __half2 w = __halves2half2(__float2half(o[dt][0] * inva),
                                       __float2half(o[dt][1] * inva));
            *(__half2*)&outa[d0] = w;
        }
        if (vb_ok) {
            __half2 w = __halves2half2(__float2half(o[dt][2] * invb),
                                       __float2half(o[dt][3] * invb));
            *(__half2*)&outb[d0] = w;
        }
    }
}

// ============================================================================
extern "C" void kernel_launch(void* const* d_in, const int* in_sizes, int n_in,
                              void* d_out, int out_size) {
    const float* x      = (const float*)d_in[0];
    const int*   pos    = (const int*)d_in[1];
    const int*   qstart = (const int*)d_in[2];
    const int*   qlens  = (const int*)d_in[3];
    const int*   kvlens = (const int*)d_in[4];
    const int*   boff   = (const int*)d_in[5];
    const float* pk     = (const float*)d_in[6];
    const float* pv     = (const float*)d_in[7];
    const float* Wq = (const float*)d_in[8];
    const float* bq = (const float*)d_in[9];
    const float* Wk = (const float*)d_in[10];
    const float* bk = (const float*)d_in[11];
    const float* Wv = (const float*)d_in[12];
    const float* bv = (const float*)d_in[13];
    const float* Wo = (const float*)d_in[14];
    const float* bo = (const float*)d_in[15];
    float* out = (float*)d_out;

    float* vp;
    cudaGetSymbolAddress((void**)&vp, g_v);
    __nv_bfloat16 *xhi, *xlo;
    __half *xh, *w3h, *w4h;
    cudaGetSymbolAddress((void**)&xhi, g_xhi);
    cudaGetSymbolAddress((void**)&xlo, g_xlo);
    cudaGetSymbolAddress((void**)&xh,  g_xh);
    cudaGetSymbolAddress((void**)&w3h, g_w3h);
    cudaGetSymbolAddress((void**)&w4h, g_w4h);

    cudaFuncSetAttribute(gemm3qk, cudaFuncAttributeMaxDynamicSharedMemorySize, GEMM3_SMEM);
    cudaFuncSetAttribute(gemm1h,  cudaFuncAttributeMaxDynamicSharedMemorySize, GEMM1_SMEM);
    cudaFuncSetAttribute(attn_kernel, cudaFuncAttributeMaxDynamicSharedMemorySize, ATTN_SMEM_BYTES);

    const int n4x = TT * HID / 4;
    const int n4w = HID * HID / 4;
    dim3 ggqk(HID / 128, TT / 128, 2);
    dim3 gg(HID / 128, TT / 128);

    wsplit_kernel<<<dim3((n4w + 255) / 256, 1, 4), 256>>>(Wq, Wk, Wv, Wo);
    xsplit3_kernel<<<(n4x + 255) / 256, 256>>>(x, n4x);
    gemm3qk<<<ggqk, 256, GEMM3_SMEM>>>(xhi, xlo, bq, bk);
    gemm1h<<<gg, 256, GEMM1_SMEM>>>(xh, w3h, bv, vp);
    init_freq_kernel<<<1, 64>>>();
    rope_kernel<<<(TT * NH * 64 + 255) / 256, 256>>>(pos);
    kvprep_kernel<<<NBAT * MAXKV, 128>>>(pk, pv, qstart, qlens, kvlens, boff);
    attn_kernel<<<dim3(16, NH, NBAT), 128, ATTN_SMEM_BYTES>>>(qstart, qlens, kvlens);
    gemm1h<<<gg, 256, GEMM1_SMEM>>>(xh, w4h, bo, out);
}